// round 3
// baseline (speedup 1.0000x reference)
#include <cuda_runtime.h>
#include <math.h>
#include <stdint.h>

#define Bb   16
#define HWd  4096
#define Dd   512
#define CLd  768
#define Kch  512
#define Vch  512
#define NLd  32
#define Hh   8
#define Mm   (Bb*HWd)

// ---------------- scratch ----------------
static __device__ float g_vis[(size_t)Mm*Dd];
static __device__ float g_q  [(size_t)Mm*Kch];
static __device__ float g_lv [(size_t)Mm*CLd];
static __device__ float g_att[(size_t)Mm*Vch];
static __device__ float g_vo [(size_t)Mm*Vch];
static __device__ float g_z  [(size_t)Mm*Vch];
static __device__ float g_sim[(size_t)Bb*Hh*HWd*NLd];
static __device__ float g_lang[Bb*CLd*NLd];
static __device__ float g_k  [Bb*Kch*NLd];
static __device__ float g_v  [Bb*Vch*NLd];
static __device__ float g_lo1[Bb*CLd*NLd];
static __device__ float g_lo2[Bb*CLd*NLd];
static __device__ float g_zt [Bb*CLd*NLd];
static __device__ float g_mq [Bb*Kch],  g_rq [Bb*Kch];
static __device__ float g_mlv[Bb*CLd],  g_rlv[Bb*CLd];
static __device__ float g_mw [Bb*Vch],  g_rw [Bb*Vch];
static __device__ float g_lmax[Bb*Hh*NLd], g_lsum[Bb*Hh*NLd];

__device__ __forceinline__ float gelu_f(float x){
    return 0.5f*x*(1.0f + erff(x*0.70710678118654752f));
}
__device__ __forceinline__ unsigned long long pack2(float x){
    unsigned long long r; unsigned u = __float_as_uint(x);
    asm("mov.b64 %0, {%1, %1};" : "=l"(r) : "r"(u));
    return r;
}
__device__ __forceinline__ void fma2(unsigned long long& d, unsigned long long a, unsigned long long b){
    asm("fma.rn.f32x2 %0, %1, %2, %0;" : "+l"(d) : "l"(a), "l"(b));
}
__device__ __forceinline__ float lo2f(unsigned long long v){ return __uint_as_float((unsigned)v); }
__device__ __forceinline__ float hi2f(unsigned long long v){ return __uint_as_float((unsigned)(v>>32)); }

// ---------------- big GEMM: C = act(A[M,K] @ W[N,K]^T + b) ----------------
__global__ __launch_bounds__(256) void sgemm_kernel(
    const float* __restrict__ A, const float* __restrict__ W,
    const float* __restrict__ bias, float* __restrict__ C, int N, int K, int act)
{
    __shared__ float As[8][136];
    __shared__ float Bs[8][136];
    const int tid = threadIdx.x, tx = tid & 15, ty = tid >> 4;
    const int m0 = blockIdx.y * 128, n0 = blockIdx.x * 128;
    const int lrow = tid >> 1, lk = (tid & 1) * 4;

    unsigned long long acc[8][4];
    #pragma unroll
    for (int i=0;i<8;i++){ acc[i][0]=0ull; acc[i][1]=0ull; acc[i][2]=0ull; acc[i][3]=0ull; }

    const float* Ap = A + (size_t)(m0 + lrow) * K + lk;
    const float* Wp = W + (size_t)(n0 + lrow) * K + lk;

    for (int k0 = 0; k0 < K; k0 += 8){
        float4 av = *(const float4*)(Ap + k0);
        float4 bv = *(const float4*)(Wp + k0);
        As[lk+0][lrow]=av.x; As[lk+1][lrow]=av.y; As[lk+2][lrow]=av.z; As[lk+3][lrow]=av.w;
        Bs[lk+0][lrow]=bv.x; Bs[lk+1][lrow]=bv.y; Bs[lk+2][lrow]=bv.z; Bs[lk+3][lrow]=bv.w;
        __syncthreads();
        #pragma unroll
        for (int kk=0;kk<8;kk++){
            float4 a0 = *(const float4*)&As[kk][ty*4];
            float4 a1 = *(const float4*)&As[kk][ty*4+64];
            ulonglong2 b0 = *(const ulonglong2*)&Bs[kk][tx*4];
            ulonglong2 b1 = *(const ulonglong2*)&Bs[kk][tx*4+64];
            unsigned long long ap[8];
            ap[0]=pack2(a0.x); ap[1]=pack2(a0.y); ap[2]=pack2(a0.z); ap[3]=pack2(a0.w);
            ap[4]=pack2(a1.x); ap[5]=pack2(a1.y); ap[6]=pack2(a1.z); ap[7]=pack2(a1.w);
            #pragma unroll
            for (int i=0;i<8;i++){
                fma2(acc[i][0], ap[i], b0.x);
                fma2(acc[i][1], ap[i], b0.y);
                fma2(acc[i][2], ap[i], b1.x);
                fma2(acc[i][3], ap[i], b1.y);
            }
        }
        __syncthreads();
    }
    float4 bs0 = *(const float4*)&bias[n0 + tx*4];
    float4 bs1 = *(const float4*)&bias[n0 + tx*4 + 64];
    #pragma unroll
    for (int i=0;i<8;i++){
        int m = m0 + ty*4 + (i & 3) + (i >> 2) * 64;
        float4 r0, r1;
        r0.x = lo2f(acc[i][0]) + bs0.x; r0.y = hi2f(acc[i][0]) + bs0.y;
        r0.z = lo2f(acc[i][1]) + bs0.z; r0.w = hi2f(acc[i][1]) + bs0.w;
        r1.x = lo2f(acc[i][2]) + bs1.x; r1.y = hi2f(acc[i][2]) + bs1.y;
        r1.z = lo2f(acc[i][3]) + bs1.z; r1.w = hi2f(acc[i][3]) + bs1.w;
        if (act){
            r0.x=gelu_f(r0.x); r0.y=gelu_f(r0.y); r0.z=gelu_f(r0.z); r0.w=gelu_f(r0.w);
            r1.x=gelu_f(r1.x); r1.y=gelu_f(r1.y); r1.z=gelu_f(r1.z); r1.w=gelu_f(r1.w);
        }
        *(float4*)&C[(size_t)m*N + n0 + tx*4]      = r0;
        *(float4*)&C[(size_t)m*N + n0 + tx*4 + 64] = r1;
    }
}

// ---------------- per-(b,c) mean/rstd over HW ----------------
__global__ void stats_kernel(const float* __restrict__ A, float* __restrict__ mean,
                             float* __restrict__ rstd, int C)
{
    const int b = blockIdx.y, c = blockIdx.x*32 + threadIdx.x, ty = threadIdx.y;
    const float* base = A + (size_t)b*HWd*C + c;
    float s=0.f, s2=0.f;
    for (int hw=ty; hw<HWd; hw+=16){ float v = base[(size_t)hw*C]; s+=v; s2+=v*v; }
    __shared__ float ss[16][33], sq[16][33];
    ss[ty][threadIdx.x]=s; sq[ty][threadIdx.x]=s2;
    __syncthreads();
    if (ty==0){
        #pragma unroll
        for (int i=1;i<16;i++){ s+=ss[i][threadIdx.x]; s2+=sq[i][threadIdx.x]; }
        float m = s*(1.f/HWd), var = s2*(1.f/HWd) - m*m;
        mean[b*C+c]=m; rstd[b*C+c]=rsqrtf(var + 1e-5f);
    }
}

// ---------------- lang 1x1 conv (Cin=768): mode 1 gelu, 2 mask, 4 transpose, 8 inorm(NL) --
__global__ __launch_bounds__(256) void lang_conv_kernel(
    const float* __restrict__ in, const float* __restrict__ w,
    const float* __restrict__ bias, const float* __restrict__ mask,
    float* __restrict__ out, int Cout, int mode)
{
    __shared__ float in_s[32][33];
    __shared__ float w_s [32][33];
    const int b = blockIdx.x, o0 = blockIdx.y*32, t = threadIdx.x;
    const int n = t & 31, og = t >> 5;
    float acc[4] = {0.f,0.f,0.f,0.f};
    for (int i0=0;i0<CLd;i0+=32){
        for (int e=t;e<1024;e+=256) in_s[e>>5][e&31] = in[((size_t)b*CLd + i0+(e>>5))*NLd + (e&31)];
        for (int e=t;e<1024;e+=256) w_s[e>>5][e&31]  = w[(size_t)(o0+(e>>5))*CLd + i0+(e&31)];
        __syncthreads();
        #pragma unroll
        for (int ii=0;ii<32;ii++){
            float iv = in_s[ii][n];
            acc[0]+=w_s[og   ][ii]*iv; acc[1]+=w_s[og+ 8][ii]*iv;
            acc[2]+=w_s[og+16][ii]*iv; acc[3]+=w_s[og+24][ii]*iv;
        }
        __syncthreads();
    }
    float mv = (mode & 2) ? mask[b*NLd + n] : 1.f;
    #pragma unroll
    for (int j=0;j<4;j++){
        int o = o0 + og + 8*j;
        float v = acc[j] + bias[o];
        if (mode & 2) v *= mv;
        if (mode & 8){
            float s=v, s2=v*v;
            #pragma unroll
            for (int off=16;off;off>>=1){ s+=__shfl_xor_sync(~0u,s,off); s2+=__shfl_xor_sync(~0u,s2,off); }
            float mn = s*(1.f/32.f), vr = s2*(1.f/32.f) - mn*mn;
            v = (v-mn)*rsqrtf(vr + 1e-5f);
        }
        if (mode & 1) v = gelu_f(v);
        if (mode & 4) out[((size_t)b*NLd + n)*Cout + o] = v;
        else          out[((size_t)b*Cout + o)*NLd + n] = v;
    }
}

// ---------------- sim = inorm(q).k * scale + 1e4*mask - 1e4 ----------------
__global__ __launch_bounds__(256) void sim_kernel(const float* __restrict__ mask)
{
    __shared__ float ks[64*32];
    __shared__ float qm[64], qr[64], mk[32];
    __shared__ float qrow[8][64];
    const int bh = blockIdx.y, b = bh>>3, h = bh&7;
    const int t = threadIdx.x, w = t>>5, lane = t&31;
    for (int e=t; e<2048; e+=256) ks[e] = g_k[((size_t)b*Kch + h*64)*NLd + e];
    if (t<64){ qm[t]=g_mq[b*Kch+h*64+t]; qr[t]=g_rq[b*Kch+h*64+t]; }
    if (t>=64 && t<96) mk[t-64]=mask[b*NLd+t-64];
    __syncthreads();
    const int hw0 = blockIdx.x*1024;
    for (int it=0; it<128; it++){
        int hw = hw0 + it*8 + w;
        const float2 q2 = ((const float2*)&g_q[((size_t)(b*HWd+hw))*Kch + h*64])[lane];
        qrow[w][2*lane  ] = (q2.x - qm[2*lane  ])*qr[2*lane  ];
        qrow[w][2*lane+1] = (q2.y - qm[2*lane+1])*qr[2*lane+1];
        __syncwarp();
        float acc=0.f;
        #pragma unroll 16
        for (int d=0; d<64; d++) acc += qrow[w][d]*ks[d*32+lane];
        g_sim[((size_t)bh*HWd+hw)*32+lane] =
            acc*0.044194173824159216f + 10000.f*mk[lane] - 10000.f;
        __syncwarp();
    }
}

// ---------------- lang->image softmax stats over HW ----------------
__global__ void latt_stats_kernel()
{
    const int bh = blockIdx.x, n = threadIdx.x, ty = threadIdx.y;
    float m = -1e30f, s = 0.f;
    for (int hw=ty; hw<HWd; hw+=32){
        float v = g_sim[((size_t)bh*HWd+hw)*32 + n];
        float nm = fmaxf(m, v);
        s = s*__expf(m-nm) + __expf(v-nm); m = nm;
    }
    __shared__ float sm[32][33], ss[32][33];
    sm[ty][n]=m; ss[ty][n]=s;
    __syncthreads();
    if (ty==0){
        for (int i=1;i<32;i++){
            float m2=sm[i][n], s2=ss[i][n], nm=fmaxf(m,m2);
            s = s*__expf(m-nm) + s2*__expf(m2-nm); m = nm;
        }
        g_lmax[bh*32+n]=m; g_lsum[bh*32+n]=s;
    }
}

// ---------------- image->lang: out = softmax_n(sim) . v ----------------
__global__ __launch_bounds__(256) void attout_kernel()
{
    __shared__ float v_s[32*68];
    const int bh=blockIdx.y, b=bh>>3, h=bh&7, t=threadIdx.x;
    for (int e=t;e<2048;e+=256) v_s[(e&31)*68+(e>>5)] = g_v[((size_t)b*Vch + h*64)*NLd + e];
    __syncthreads();
    const int hw = blockIdx.x*256 + t;
    const float4* sp = (const float4*)&g_sim[((size_t)bh*HWd+hw)*32];
    float sv[32];
    #pragma unroll
    for (int j=0;j<8;j++){ float4 s4=sp[j]; sv[4*j]=s4.x; sv[4*j+1]=s4.y; sv[4*j+2]=s4.z; sv[4*j+3]=s4.w; }
    float mx=-1e30f;
    #pragma unroll
    for (int i=0;i<32;i++) mx=fmaxf(mx,sv[i]);
    float sum=0.f;
    #pragma unroll
    for (int i=0;i<32;i++){ sv[i]=__expf(sv[i]-mx); sum+=sv[i]; }
    float inv=1.f/sum;
    float acc[64];
    #pragma unroll
    for (int i=0;i<64;i++) acc[i]=0.f;
    #pragma unroll 4
    for (int n=0;n<32;n++){
        float a = sv[n]*inv;
        const float4* vr = (const float4*)&v_s[n*68];
        #pragma unroll
        for (int j=0;j<16;j++){
            float4 vv = vr[j];
            acc[4*j]+=a*vv.x; acc[4*j+1]+=a*vv.y; acc[4*j+2]+=a*vv.z; acc[4*j+3]+=a*vv.w;
        }
    }
    float4* op = (float4*)&g_att[((size_t)(b*HWd+hw))*Vch + h*64];
    #pragma unroll
    for (int j=0;j<16;j++){ float4 o; o.x=acc[4*j]; o.y=acc[4*j+1]; o.z=acc[4*j+2]; o.w=acc[4*j+3]; op[j]=o; }
}

// ---------------- lang_out = (latt . inorm(lv)) * mask ----------------
__global__ __launch_bounds__(256) void langout_kernel(const float* __restrict__ mask)
{
    __shared__ float ps[32*32];
    __shared__ float lvs[32*96];
    __shared__ float lmx[32], lsm[32];
    const int bh=blockIdx.x, b=bh>>3, h=bh&7, t=threadIdx.x;
    if (t<32){ lmx[t]=g_lmax[bh*32+t]; lsm[t]=1.f/g_lsum[bh*32+t]; }
    __syncthreads();
    const int n=t&31, c0=(t>>5)*12;
    float acc[12];
    #pragma unroll
    for (int j=0;j<12;j++) acc[j]=0.f;
    for (int hw0=0; hw0<HWd; hw0+=32){
        for (int e=t;e<1024;e+=256){
            int r=e>>5, nn=e&31;
            ps[e]=__expf(g_sim[((size_t)bh*HWd+hw0+r)*32+nn]-lmx[nn])*lsm[nn];
        }
        for (int e=t;e<3072;e+=256){
            int r=e/96, cc=e-r*96, ch=h*96+cc;
            lvs[e]=(g_lv[((size_t)(b*HWd+hw0+r))*CLd+ch]-g_mlv[b*CLd+ch])*g_rlv[b*CLd+ch];
        }
        __syncthreads();
        #pragma unroll 8
        for (int r=0;r<32;r++){
            float p=ps[r*32+n];
            #pragma unroll
            for (int j=0;j<12;j++) acc[j]+=p*lvs[r*96+c0+j];
        }
        __syncthreads();
    }
    float mv = mask[b*NLd+n];
    #pragma unroll
    for (int j=0;j<12;j++)
        g_lo1[((size_t)b*CLd + h*96+c0+j)*NLd + n] = acc[j]*mv;
}

// ---------------- elementwise: z = vis * inorm(vo) ----------------
__global__ void zmul_kernel()
{
    size_t i = ((size_t)blockIdx.x*256 + threadIdx.x)*4;
    int c = (int)(i & 511);
    size_t m = i >> 9;
    int b = (int)(m >> 12);
    float4 vi = *(const float4*)&g_vis[i];
    float4 vo = *(const float4*)&g_vo[i];
    float4 r;
    r.x = vi.x*(vo.x-g_mw[b*Vch+c  ])*g_rw[b*Vch+c  ];
    r.y = vi.y*(vo.y-g_mw[b*Vch+c+1])*g_rw[b*Vch+c+1];
    r.z = vi.z*(vo.z-g_mw[b*Vch+c+2])*g_rw[b*Vch+c+2];
    r.w = vi.w*(vo.w-g_mw[b*Vch+c+3])*g_rw[b*Vch+c+3];
    *(float4*)&g_z[i] = r;
}

// ---------------- elementwise: zt = lang * lang_out2 ----------------
__global__ void ztmul_kernel()
{
    size_t i = ((size_t)blockIdx.x*256 + threadIdx.x)*4;
    float4 a = *(const float4*)&g_lang[i];
    float4 b4 = *(const float4*)&g_lo2[i];
    float4 r; r.x=a.x*b4.x; r.y=a.y*b4.y; r.z=a.z*b4.z; r.w=a.w*b4.w;
    *(float4*)&g_zt[i] = r;
}

extern "C" void kernel_launch(void* const* d_in, const int* in_sizes, int n_in,
                              void* d_out, int out_size)
{
    const float* x      = (const float*)d_in[0];
    const float* l      = (const float*)d_in[1];
    const float* lmask  = (const float*)d_in[2];
    const float* w_vis  = (const float*)d_in[3];  const float* b_vis  = (const float*)d_in[4];
    const float* w_langp= (const float*)d_in[5];  const float* b_langp= (const float*)d_in[6];
    const float* w_q    = (const float*)d_in[7];  const float* b_q    = (const float*)d_in[8];
    const float* w_k    = (const float*)d_in[9];  const float* b_k    = (const float*)d_in[10];
    const float* w_v    = (const float*)d_in[11]; const float* b_v    = (const float*)d_in[12];
    const float* w_lv   = (const float*)d_in[13]; const float* b_lv   = (const float*)d_in[14];
    const float* w_W    = (const float*)d_in[15]; const float* b_W    = (const float*)d_in[16];
    const float* w_langW= (const float*)d_in[17]; const float* b_langW= (const float*)d_in[18];
    const float* w_mm   = (const float*)d_in[19]; const float* b_mm   = (const float*)d_in[20];
    const float* w_langmm=(const float*)d_in[21]; const float* b_langmm=(const float*)d_in[22];
    float* out = (float*)d_out;

    float *p_vis, *p_q, *p_lv, *p_att, *p_vo, *p_z, *p_lang, *p_k, *p_v, *p_lo1, *p_lo2, *p_zt;
    float *p_mq, *p_rq, *p_mlv, *p_rlv, *p_mw, *p_rw;
    cudaGetSymbolAddress((void**)&p_vis, g_vis);  cudaGetSymbolAddress((void**)&p_q,  g_q);
    cudaGetSymbolAddress((void**)&p_lv,  g_lv);   cudaGetSymbolAddress((void**)&p_att,g_att);
    cudaGetSymbolAddress((void**)&p_vo,  g_vo);   cudaGetSymbolAddress((void**)&p_z,  g_z);
    cudaGetSymbolAddress((void**)&p_lang,g_lang); cudaGetSymbolAddress((void**)&p_k,  g_k);
    cudaGetSymbolAddress((void**)&p_v,   g_v);    cudaGetSymbolAddress((void**)&p_lo1,g_lo1);
    cudaGetSymbolAddress((void**)&p_lo2, g_lo2);  cudaGetSymbolAddress((void**)&p_zt, g_zt);
    cudaGetSymbolAddress((void**)&p_mq,  g_mq);   cudaGetSymbolAddress((void**)&p_rq, g_rq);
    cudaGetSymbolAddress((void**)&p_mlv, g_mlv);  cudaGetSymbolAddress((void**)&p_rlv,g_rlv);
    cudaGetSymbolAddress((void**)&p_mw,  g_mw);   cudaGetSymbolAddress((void**)&p_rw, g_rw);

    dim3 blk256(256);
    // big GEMMs from x
    sgemm_kernel<<<dim3(Dd/128,  Mm/128), blk256>>>(x, w_vis, b_vis, p_vis, Dd,  Dd, 1);
    sgemm_kernel<<<dim3(Kch/128, Mm/128), blk256>>>(x, w_q,   b_q,   p_q,   Kch, Dd, 0);
    sgemm_kernel<<<dim3(CLd/128, Mm/128), blk256>>>(x, w_lv,  b_lv,  p_lv,  CLd, Dd, 0);
    stats_kernel<<<dim3(Kch/32, Bb), dim3(32,16)>>>(p_q,  p_mq,  p_rq,  Kch);
    stats_kernel<<<dim3(CLd/32, Bb), dim3(32,16)>>>(p_lv, p_mlv, p_rlv, CLd);
    // lang-side convs
    lang_conv_kernel<<<dim3(Bb, CLd/32), blk256>>>(l, w_langp, b_langp, lmask, p_lang, CLd, 1);
    lang_conv_kernel<<<dim3(Bb, Kch/32), blk256>>>(l, w_k, b_k, lmask, p_k, Kch, 2);
    lang_conv_kernel<<<dim3(Bb, Vch/32), blk256>>>(l, w_v, b_v, lmask, p_v, Vch, 2);
    // attention
    sim_kernel<<<dim3(HWd/1024, Bb*Hh), blk256>>>(lmask);
    latt_stats_kernel<<<Bb*Hh, dim3(32,32)>>>();
    attout_kernel<<<dim3(HWd/256, Bb*Hh), blk256>>>();
    langout_kernel<<<Bb*Hh, blk256>>>(lmask);
    // lang_out2 = inorm(conv(lang_out, w_langW))
    lang_conv_kernel<<<dim3(Bb, CLd/32), blk256>>>(p_lo1, w_langW, b_langW, lmask, p_lo2, CLd, 8);
    // vis_out = inorm(conv(att_out, w_W))
    sgemm_kernel<<<dim3(Vch/128, Mm/128), blk256>>>(p_att, w_W, b_W, p_vo, Vch, Vch, 0);
    stats_kernel<<<dim3(Vch/32, Bb), dim3(32,16)>>>(p_vo, p_mw, p_rw, Vch);
    zmul_kernel<<<(int)(((size_t)Mm*Vch)/1024), blk256>>>();
    // mm = gelu(conv(z, w_mm)) -> out[0 : M*V]
    sgemm_kernel<<<dim3(Vch/128, Mm/128), blk256>>>(p_z, w_mm, b_mm, out, Vch, Vch, 1);
    // lang_mm = gelu(conv(lang*lo2, w_langmm)) transposed -> out[M*V : ]
    ztmul_kernel<<<(Bb*CLd*NLd)/1024, blk256>>>();
    lang_conv_kernel<<<dim3(Bb, CLd/32), blk256>>>(p_zt, w_langmm, b_langmm, lmask,
                                                   out + (size_t)Mm*Vch, CLd, 1|4);
    (void)in_sizes; (void)n_in; (void)out_size;
}

// round 6
// speedup vs baseline: 1.2387x; 1.2387x over previous
#include <cuda_runtime.h>
#include <cuda_bf16.h>
#include <math.h>
#include <stdint.h>

#define Bb   16
#define HWd  4096
#define Dd   512
#define CLd  768
#define Kch  512
#define Vch  512
#define NLd  32
#define Hh   8
#define Mm   (Bb*HWd)

// ---------------- scratch ----------------
static __device__ float g_vis[(size_t)Mm*Dd];
static __device__ float g_q  [(size_t)Mm*Kch];
static __device__ float g_lv [(size_t)Mm*CLd];
static __device__ float g_att[(size_t)Mm*Vch];
static __device__ float g_vo [(size_t)Mm*Vch];
static __device__ float g_z  [(size_t)Mm*Vch];
static __device__ float g_sim[(size_t)Bb*Hh*HWd*NLd];
static __device__ float g_lang[Bb*CLd*NLd];
static __device__ float g_k  [Bb*Kch*NLd];
static __device__ float g_v  [Bb*Vch*NLd];
static __device__ float g_lo1[Bb*CLd*NLd];
static __device__ float g_lo2[Bb*CLd*NLd];
static __device__ float g_zt [Bb*CLd*NLd];
static __device__ float g_mq [Bb*Kch],  g_rq [Bb*Kch];
static __device__ float g_mlv[Bb*CLd],  g_rlv[Bb*CLd];
static __device__ float g_mw [Bb*Vch],  g_rw [Bb*Vch];
static __device__ float g_lmax[Bb*Hh*NLd], g_lsum[Bb*Hh*NLd];

__device__ __forceinline__ float gelu_f(float x){
    return 0.5f*x*(1.0f + erff(x*0.70710678118654752f));
}

// ---------------- HMMA GEMM: C[M,N] = act(A[M,K] @ W[N,K]^T + b) ----------------
// mma.sync m16n8k16 bf16, 3-pass hi/lo split for near-fp32 accuracy.
// CTA tile 128x128, BK=32, 8 warps each m32 x n64.
#define GP 40   // padded row stride (elements) -> 80B, conflict-free fragment LDS

__device__ __forceinline__ void mma16816(float* c, const uint32_t* a, const uint32_t* b){
    asm volatile("mma.sync.aligned.m16n8k16.row.col.f32.bf16.bf16.f32 "
        "{%0,%1,%2,%3}, {%4,%5,%6,%7}, {%8,%9}, {%0,%1,%2,%3};"
        : "+f"(c[0]),"+f"(c[1]),"+f"(c[2]),"+f"(c[3])
        : "r"(a[0]),"r"(a[1]),"r"(a[2]),"r"(a[3]), "r"(b[0]),"r"(b[1]));
}
__device__ __forceinline__ uint32_t bfpack(float x, float y){
    __nv_bfloat162 t; t.x = __float2bfloat16(x); t.y = __float2bfloat16(y);
    return *(uint32_t*)&t;
}

__global__ __launch_bounds__(256) void tc_gemm(
    const float* __restrict__ A, const float* __restrict__ Wt,
    const float* __restrict__ bias, float* __restrict__ C,
    int N, int K, int act)
{
    __shared__ __nv_bfloat16 sA[2][128*GP];   // [hi/lo][row*GP + k]
    __shared__ __nv_bfloat16 sW[2][128*GP];

    const int t = threadIdx.x, lane = t & 31, wid = t >> 5;
    const int m0 = blockIdx.y * 128, n0 = blockIdx.x * 128;
    const int wm = (wid & 3) * 32, wn = (wid >> 2) * 64;
    const int fr = lane >> 2, fc = (lane & 3) * 2;

    float acc[2][8][4];
    #pragma unroll
    for (int i=0;i<2;i++)
        #pragma unroll
        for (int j=0;j<8;j++){ acc[i][j][0]=0.f; acc[i][j][1]=0.f; acc[i][j][2]=0.f; acc[i][j][3]=0.f; }

    const int niter = K >> 5;
    for (int it = 0; it < niter; it++){
        if (it) __syncthreads();
        const int k0 = it << 5;
        // stage A and W tiles: fp32 -> hi/lo bf16
        #pragma unroll
        for (int i = 0; i < 4; i++){
            int q = t + i * 256;
            int row = q >> 3, kc = (q & 7) << 2;
            float4 a = *(const float4*)(A + (size_t)(m0 + row) * K + k0 + kc);
            uint32_t h0 = bfpack(a.x, a.y), h1 = bfpack(a.z, a.w);
            float hx = __bfloat162float(__float2bfloat16(a.x));
            float hy = __bfloat162float(__float2bfloat16(a.y));
            float hz = __bfloat162float(__float2bfloat16(a.z));
            float hw = __bfloat162float(__float2bfloat16(a.w));
            uint32_t l0 = bfpack(a.x - hx, a.y - hy), l1 = bfpack(a.z - hz, a.w - hw);
            uint32_t off = row * GP + kc;
            *(uint32_t*)&sA[0][off] = h0; *(uint32_t*)&sA[0][off + 2] = h1;
            *(uint32_t*)&sA[1][off] = l0; *(uint32_t*)&sA[1][off + 2] = l1;

            float4 w = *(const float4*)(Wt + (size_t)(n0 + row) * K + k0 + kc);
            uint32_t wh0 = bfpack(w.x, w.y), wh1 = bfpack(w.z, w.w);
            float gx = __bfloat162float(__float2bfloat16(w.x));
            float gy = __bfloat162float(__float2bfloat16(w.y));
            float gz = __bfloat162float(__float2bfloat16(w.z));
            float gw = __bfloat162float(__float2bfloat16(w.w));
            uint32_t wl0 = bfpack(w.x - gx, w.y - gy), wl1 = bfpack(w.z - gz, w.w - gw);
            *(uint32_t*)&sW[0][off] = wh0; *(uint32_t*)&sW[0][off + 2] = wh1;
            *(uint32_t*)&sW[1][off] = wl0; *(uint32_t*)&sW[1][off + 2] = wl1;
        }
        __syncthreads();

        #pragma unroll
        for (int ks = 0; ks < 2; ks++){
            const int kk = ks * 16;
            uint32_t ah[2][4], al[2][4];
            #pragma unroll
            for (int mi = 0; mi < 2; mi++){
                int r = wm + mi * 16 + fr;
                ah[mi][0] = *(const uint32_t*)&sA[0][(r    ) * GP + kk + fc];
                ah[mi][1] = *(const uint32_t*)&sA[0][(r + 8) * GP + kk + fc];
                ah[mi][2] = *(const uint32_t*)&sA[0][(r    ) * GP + kk + fc + 8];
                ah[mi][3] = *(const uint32_t*)&sA[0][(r + 8) * GP + kk + fc + 8];
                al[mi][0] = *(const uint32_t*)&sA[1][(r    ) * GP + kk + fc];
                al[mi][1] = *(const uint32_t*)&sA[1][(r + 8) * GP + kk + fc];
                al[mi][2] = *(const uint32_t*)&sA[1][(r    ) * GP + kk + fc + 8];
                al[mi][3] = *(const uint32_t*)&sA[1][(r + 8) * GP + kk + fc + 8];
            }
            uint32_t bh[8][2], bl[8][2];
            #pragma unroll
            for (int ni = 0; ni < 8; ni++){
                int n = wn + ni * 8 + fr;
                bh[ni][0] = *(const uint32_t*)&sW[0][n * GP + kk + fc];
                bh[ni][1] = *(const uint32_t*)&sW[0][n * GP + kk + fc + 8];
                bl[ni][0] = *(const uint32_t*)&sW[1][n * GP + kk + fc];
                bl[ni][1] = *(const uint32_t*)&sW[1][n * GP + kk + fc + 8];
            }
            #pragma unroll
            for (int mi = 0; mi < 2; mi++)
                #pragma unroll
                for (int ni = 0; ni < 8; ni++){
                    mma16816(acc[mi][ni], ah[mi], bh[ni]);
                    mma16816(acc[mi][ni], ah[mi], bl[ni]);
                    mma16816(acc[mi][ni], al[mi], bh[ni]);
                }
        }
    }

    // epilogue
    #pragma unroll
    for (int mi = 0; mi < 2; mi++){
        #pragma unroll
        for (int ni = 0; ni < 8; ni++){
            int m = m0 + wm + mi * 16 + fr;
            int n = n0 + wn + ni * 8 + fc;
            float b0 = bias[n], b1 = bias[n + 1];
            float v0 = acc[mi][ni][0] + b0, v1 = acc[mi][ni][1] + b1;
            float v2 = acc[mi][ni][2] + b0, v3 = acc[mi][ni][3] + b1;
            if (act){ v0 = gelu_f(v0); v1 = gelu_f(v1); v2 = gelu_f(v2); v3 = gelu_f(v3); }
            *(float2*)&C[(size_t)m * N + n]       = make_float2(v0, v1);
            *(float2*)&C[(size_t)(m + 8) * N + n] = make_float2(v2, v3);
        }
    }
}

// ---------------- per-(b,c) mean/rstd over HW (fp64 accumulation) ----------------
__global__ void stats_kernel(const float* __restrict__ A, float* __restrict__ mean,
                             float* __restrict__ rstd, int C)
{
    const int b = blockIdx.y, c = blockIdx.x*32 + threadIdx.x, ty = threadIdx.y;
    const float* base = A + (size_t)b*HWd*C + c;
    double s = 0.0, s2 = 0.0;
    for (int hw = ty; hw < HWd; hw += 32){
        double v = (double)base[(size_t)hw*C];
        s += v; s2 += v*v;
    }
    __shared__ double ss[32][33], sq[32][33];
    ss[ty][threadIdx.x] = s; sq[ty][threadIdx.x] = s2;
    __syncthreads();
    if (ty == 0){
        #pragma unroll
        for (int i = 1; i < 32; i++){ s += ss[i][threadIdx.x]; s2 += sq[i][threadIdx.x]; }
        double m = s * (1.0/HWd), var = s2 * (1.0/HWd) - m*m;
        mean[b*C+c] = (float)m;
        rstd[b*C+c] = (float)(1.0 / sqrt(var + 1e-5));
    }
}

// ---------------- lang 1x1 conv: mode 1 gelu, 2 mask, 4 transpose, 8 inorm(NL) ----
__global__ __launch_bounds__(256) void lang_conv_kernel(
    const float* __restrict__ in, const float* __restrict__ w,
    const float* __restrict__ bias, const float* __restrict__ mask,
    float* __restrict__ out, int Cout, int mode)
{
    __shared__ float in_s[32][33];
    __shared__ float w_s [32][33];
    const int b = blockIdx.x, o0 = blockIdx.y*32, t = threadIdx.x;
    const int n = t & 31, og = t >> 5;
    float acc[4] = {0.f,0.f,0.f,0.f};
    for (int i0 = 0; i0 < CLd; i0 += 32){
        for (int e = t; e < 1024; e += 256) in_s[e>>5][e&31] = in[((size_t)b*CLd + i0+(e>>5))*NLd + (e&31)];
        for (int e = t; e < 1024; e += 256) w_s[e>>5][e&31]  = w[(size_t)(o0+(e>>5))*CLd + i0+(e&31)];
        __syncthreads();
        #pragma unroll
        for (int ii = 0; ii < 32; ii++){
            float iv = in_s[ii][n];
            acc[0]+=w_s[og   ][ii]*iv; acc[1]+=w_s[og+ 8][ii]*iv;
            acc[2]+=w_s[og+16][ii]*iv; acc[3]+=w_s[og+24][ii]*iv;
        }
        __syncthreads();
    }
    float mv = (mode & 2) ? mask[b*NLd + n] : 1.f;
    #pragma unroll
    for (int j = 0; j < 4; j++){
        int o = o0 + og + 8*j;
        float v = acc[j] + bias[o];
        if (mode & 2) v *= mv;
        if (mode & 8){
            float s=v, s2=v*v;
            #pragma unroll
            for (int off=16;off;off>>=1){ s+=__shfl_xor_sync(~0u,s,off); s2+=__shfl_xor_sync(~0u,s2,off); }
            float mn = s*(1.f/32.f), vr = s2*(1.f/32.f) - mn*mn;
            v = (v-mn)*rsqrtf(vr + 1e-5f);
        }
        if (mode & 1) v = gelu_f(v);
        if (mode & 4) out[((size_t)b*NLd + n)*Cout + o] = v;
        else          out[((size_t)b*Cout + o)*NLd + n] = v;
    }
}

// ---------------- sim = inorm(q).k * scale + 1e4*mask - 1e4 ----------------
__global__ __launch_bounds__(256) void sim_kernel(const float* __restrict__ mask)
{
    __shared__ float ks[64*32];
    __shared__ float qm[64], qr[64], mk[32];
    __shared__ float qrow[8][64];
    const int bh = blockIdx.y, b = bh>>3, h = bh&7;
    const int t = threadIdx.x, w = t>>5, lane = t&31;
    for (int e = t; e < 2048; e += 256) ks[e] = g_k[((size_t)b*Kch + h*64)*NLd + e];
    if (t < 64){ qm[t]=g_mq[b*Kch+h*64+t]; qr[t]=g_rq[b*Kch+h*64+t]; }
    if (t >= 64 && t < 96) mk[t-64]=mask[b*NLd+t-64];
    __syncthreads();
    const int hw0 = blockIdx.x*1024;
    for (int it = 0; it < 128; it++){
        int hw = hw0 + it*8 + w;
        const float2 q2 = ((const float2*)&g_q[((size_t)(b*HWd+hw))*Kch + h*64])[lane];
        qrow[w][2*lane  ] = (q2.x - qm[2*lane  ])*qr[2*lane  ];
        qrow[w][2*lane+1] = (q2.y - qm[2*lane+1])*qr[2*lane+1];
        __syncwarp();
        float acc = 0.f;
        #pragma unroll 16
        for (int d = 0; d < 64; d++) acc += qrow[w][d]*ks[d*32+lane];
        g_sim[((size_t)bh*HWd+hw)*32+lane] =
            acc*0.044194173824159216f + 10000.f*mk[lane] - 10000.f;
        __syncwarp();
    }
}

// ---------------- lang->image softmax stats over HW ----------------
__global__ void latt_stats_kernel()
{
    const int bh = blockIdx.x, n = threadIdx.x, ty = threadIdx.y;
    float m = -1e30f, s = 0.f;
    for (int hw = ty; hw < HWd; hw += 32){
        float v = g_sim[((size_t)bh*HWd+hw)*32 + n];
        float nm = fmaxf(m, v);
        s = s*__expf(m-nm) + __expf(v-nm); m = nm;
    }
    __shared__ float sm_[32][33], ss[32][33];
    sm_[ty][n]=m; ss[ty][n]=s;
    __syncthreads();
    if (ty == 0){
        for (int i = 1; i < 32; i++){
            float m2=sm_[i][n], s2=ss[i][n], nm=fmaxf(m,m2);
            s = s*__expf(m-nm) + s2*__expf(m2-nm); m = nm;
        }
        g_lmax[bh*32+n]=m; g_lsum[bh*32+n]=s;
    }
}

// ---------------- image->lang: out = softmax_n(sim) . v ----------------
__global__ __launch_bounds__(256) void attout_kernel()
{
    __shared__ float v_s[32*68];
    const int bh=blockIdx.y, b=bh>>3, h=bh&7, t=threadIdx.x;
    for (int e=t;e<2048;e+=256) v_s[(e&31)*68+(e>>5)] = g_v[((size_t)b*Vch + h*64)*NLd + e];
    __syncthreads();
    const int hw = blockIdx.x*256 + t;
    const float4* sp = (const float4*)&g_sim[((size_t)bh*HWd+hw)*32];
    float sv[32];
    #pragma unroll
    for (int j=0;j<8;j++){ float4 s4=sp[j]; sv[4*j]=s4.x; sv[4*j+1]=s4.y; sv[4*j+2]=s4.z; sv[4*j+3]=s4.w; }
    float mx=-1e30f;
    #pragma unroll
    for (int i=0;i<32;i++) mx=fmaxf(mx,sv[i]);
    float sum=0.f;
    #pragma unroll
    for (int i=0;i<32;i++){ sv[i]=__expf(sv[i]-mx); sum+=sv[i]; }
    float inv=1.f/sum;
    float acc[64];
    #pragma unroll
    for (int i=0;i<64;i++) acc[i]=0.f;
    #pragma unroll 4
    for (int n=0;n<32;n++){
        float a = sv[n]*inv;
        const float4* vr = (const float4*)&v_s[n*68];
        #pragma unroll
        for (int j=0;j<16;j++){
            float4 vv = vr[j];
            acc[4*j]+=a*vv.x; acc[4*j+1]+=a*vv.y; acc[4*j+2]+=a*vv.z; acc[4*j+3]+=a*vv.w;
        }
    }
    float4* op = (float4*)&g_att[((size_t)(b*HWd+hw))*Vch + h*64];
    #pragma unroll
    for (int j=0;j<16;j++){ float4 o; o.x=acc[4*j]; o.y=acc[4*j+1]; o.z=acc[4*j+2]; o.w=acc[4*j+3]; op[j]=o; }
}

// ---------------- lang_out = (latt . inorm(lv)) * mask ----------------
__global__ __launch_bounds__(256) void langout_kernel(const float* __restrict__ mask)
{
    __shared__ float ps[32*32];
    __shared__ float lvs[32*96];
    __shared__ float lmx[32], lsm[32];
    const int bh=blockIdx.x, b=bh>>3, h=bh&7, t=threadIdx.x;
    if (t<32){ lmx[t]=g_lmax[bh*32+t]; lsm[t]=1.f/g_lsum[bh*32+t]; }
    __syncthreads();
    const int n=t&31, c0=(t>>5)*12;
    float acc[12];
    #pragma unroll
    for (int j=0;j<12;j++) acc[j]=0.f;
    for (int hw0=0; hw0<HWd; hw0+=32){
        for (int e=t;e<1024;e+=256){
            int r=e>>5, nn=e&31;
            ps[e]=__expf(g_sim[((size_t)bh*HWd+hw0+r)*32+nn]-lmx[nn])*lsm[nn];
        }
        for (int e=t;e<3072;e+=256){
            int r=e/96, cc=e-r*96, ch=h*96+cc;
            lvs[e]=(g_lv[((size_t)(b*HWd+hw0+r))*CLd+ch]-g_mlv[b*CLd+ch])*g_rlv[b*CLd+ch];
        }
        __syncthreads();
        #pragma unroll 8
        for (int r=0;r<32;r++){
            float p=ps[r*32+n];
            #pragma unroll
            for (int j=0;j<12;j++) acc[j]+=p*lvs[r*96+c0+j];
        }
        __syncthreads();
    }
    float mv = mask[b*NLd+n];
    #pragma unroll
    for (int j=0;j<12;j++)
        g_lo1[((size_t)b*CLd + h*96+c0+j)*NLd + n] = acc[j]*mv;
}

// ---------------- elementwise: z = vis * inorm(vo) ----------------
__global__ void zmul_kernel()
{
    size_t i = ((size_t)blockIdx.x*256 + threadIdx.x)*4;
    int c = (int)(i & 511);
    size_t m = i >> 9;
    int b = (int)(m >> 12);
    float4 vi = *(const float4*)&g_vis[i];
    float4 vo = *(const float4*)&g_vo[i];
    float4 r;
    r.x = vi.x*(vo.x-g_mw[b*Vch+c  ])*g_rw[b*Vch+c  ];
    r.y = vi.y*(vo.y-g_mw[b*Vch+c+1])*g_rw[b*Vch+c+1];
    r.z = vi.z*(vo.z-g_mw[b*Vch+c+2])*g_rw[b*Vch+c+2];
    r.w = vi.w*(vo.w-g_mw[b*Vch+c+3])*g_rw[b*Vch+c+3];
    *(float4*)&g_z[i] = r;
}

// ---------------- elementwise: zt = lang * lang_out2 ----------------
__global__ void ztmul_kernel()
{
    size_t i = ((size_t)blockIdx.x*256 + threadIdx.x)*4;
    float4 a = *(const float4*)&g_lang[i];
    float4 b4 = *(const float4*)&g_lo2[i];
    float4 r; r.x=a.x*b4.x; r.y=a.y*b4.y; r.z=a.z*b4.z; r.w=a.w*b4.w;
    *(float4*)&g_zt[i] = r;
}

extern "C" void kernel_launch(void* const* d_in, const int* in_sizes, int n_in,
                              void* d_out, int out_size)
{
    const float* x      = (const float*)d_in[0];
    const float* l      = (const float*)d_in[1];
    const float* lmask  = (const float*)d_in[2];
    const float* w_vis  = (const float*)d_in[3];  const float* b_vis  = (const float*)d_in[4];
    const float* w_langp= (const float*)d_in[5];  const float* b_langp= (const float*)d_in[6];
    const float* w_q    = (const float*)d_in[7];  const float* b_q    = (const float*)d_in[8];
    const float* w_k    = (const float*)d_in[9];  const float* b_k    = (const float*)d_in[10];
    const float* w_v    = (const float*)d_in[11]; const float* b_v    = (const float*)d_in[12];
    const float* w_lv   = (const float*)d_in[13]; const float* b_lv   = (const float*)d_in[14];
    const float* w_W    = (const float*)d_in[15]; const float* b_W    = (const float*)d_in[16];
    const float* w_langW= (const float*)d_in[17]; const float* b_langW= (const float*)d_in[18];
    const float* w_mm   = (const float*)d_in[19]; const float* b_mm   = (const float*)d_in[20];
    const float* w_langmm=(const float*)d_in[21]; const float* b_langmm=(const float*)d_in[22];
    float* out = (float*)d_out;

    float *p_vis, *p_q, *p_lv, *p_att, *p_vo, *p_z, *p_lang, *p_k, *p_v, *p_lo1, *p_lo2, *p_zt;
    float *p_mq, *p_rq, *p_mlv, *p_rlv, *p_mw, *p_rw;
    cudaGetSymbolAddress((void**)&p_vis, g_vis);  cudaGetSymbolAddress((void**)&p_q,  g_q);
    cudaGetSymbolAddress((void**)&p_lv,  g_lv);   cudaGetSymbolAddress((void**)&p_att,g_att);
    cudaGetSymbolAddress((void**)&p_vo,  g_vo);   cudaGetSymbolAddress((void**)&p_z,  g_z);
    cudaGetSymbolAddress((void**)&p_lang,g_lang); cudaGetSymbolAddress((void**)&p_k,  g_k);
    cudaGetSymbolAddress((void**)&p_v,   g_v);    cudaGetSymbolAddress((void**)&p_lo1,g_lo1);
    cudaGetSymbolAddress((void**)&p_lo2, g_lo2);  cudaGetSymbolAddress((void**)&p_zt, g_zt);
    cudaGetSymbolAddress((void**)&p_mq,  g_mq);   cudaGetSymbolAddress((void**)&p_rq, g_rq);
    cudaGetSymbolAddress((void**)&p_mlv, g_mlv);  cudaGetSymbolAddress((void**)&p_rlv,g_rlv);
    cudaGetSymbolAddress((void**)&p_mw,  g_mw);   cudaGetSymbolAddress((void**)&p_rw, g_rw);

    dim3 blk256(256);
    // big GEMMs (HMMA bf16 3-pass split)
    tc_gemm<<<dim3(Dd/128,  Mm/128), blk256>>>(x, w_vis, b_vis, p_vis, Dd,  Dd, 1);
    tc_gemm<<<dim3(Kch/128, Mm/128), blk256>>>(x, w_q,   b_q,   p_q,   Kch, Dd, 0);
    tc_gemm<<<dim3(CLd/128, Mm/128), blk256>>>(x, w_lv,  b_lv,  p_lv,  CLd, Dd, 0);
    stats_kernel<<<dim3(Kch/32, Bb), dim3(32,32)>>>(p_q,  p_mq,  p_rq,  Kch);
    stats_kernel<<<dim3(CLd/32, Bb), dim3(32,32)>>>(p_lv, p_mlv, p_rlv, CLd);
    // lang-side convs
    lang_conv_kernel<<<dim3(Bb, CLd/32), blk256>>>(l, w_langp, b_langp, lmask, p_lang, CLd, 1);
    lang_conv_kernel<<<dim3(Bb, Kch/32), blk256>>>(l, w_k, b_k, lmask, p_k, Kch, 2);
    lang_conv_kernel<<<dim3(Bb, Vch/32), blk256>>>(l, w_v, b_v, lmask, p_v, Vch, 2);
    // attention
    sim_kernel<<<dim3(HWd/1024, Bb*Hh), blk256>>>(lmask);
    latt_stats_kernel<<<Bb*Hh, dim3(32,32)>>>();
    attout_kernel<<<dim3(HWd/256, Bb*Hh), blk256>>>();
    langout_kernel<<<Bb*Hh, blk256>>>(lmask);
    // lang_out2 = inorm(conv(lang_out, w_langW))
    lang_conv_kernel<<<dim3(Bb, CLd/32), blk256>>>(p_lo1, w_langW, b_langW, lmask, p_lo2, CLd, 8);
    // vis_out = inorm(conv(att_out, w_W))
    tc_gemm<<<dim3(Vch/128, Mm/128), blk256>>>(p_att, w_W, b_W, p_vo, Vch, Vch, 0);
    stats_kernel<<<dim3(Vch/32, Bb), dim3(32,32)>>>(p_vo, p_mw, p_rw, Vch);
    zmul_kernel<<<(int)(((size_t)Mm*Vch)/1024), blk256>>>();
    // mm = gelu(conv(z, w_mm)) -> out[0 : M*V]
    tc_gemm<<<dim3(Vch/128, Mm/128), blk256>>>(p_z, w_mm, b_mm, out, Vch, Vch, 1);
    // lang_mm = gelu(conv(lang*lo2, w_langmm)) transposed -> out tail
    ztmul_kernel<<<(Bb*CLd*NLd)/1024, blk256>>>();
    lang_conv_kernel<<<dim3(Bb, CLd/32), blk256>>>(p_zt, w_langmm, b_langmm, lmask,
                                                   out + (size_t)Mm*Vch, CLd, 1|4);
    (void)in_sizes; (void)n_in; (void)out_size;
}

// round 7
// speedup vs baseline: 1.2496x; 1.0089x over previous
#include <cuda_runtime.h>
#include <cuda_bf16.h>
#include <math.h>
#include <stdint.h>

#define Bb   16
#define HWd  4096
#define Dd   512
#define CLd  768
#define Kch  512
#define Vch  512
#define NLd  32
#define Hh   8
#define Mm   (Bb*HWd)
#define SPL  8

// ---------------- scratch ----------------
static __device__ float g_vis[(size_t)Mm*Dd];
static __device__ float g_q  [(size_t)Mm*Kch];
static __device__ float g_lv [(size_t)Mm*CLd];
static __device__ float g_att[(size_t)Mm*Vch];
static __device__ float g_vo [(size_t)Mm*Vch];
static __device__ float g_sim[(size_t)Bb*Hh*HWd*NLd];
static __device__ float g_lang[Bb*CLd*NLd];
static __device__ float g_k  [Bb*Kch*NLd];
static __device__ float g_v  [Bb*Vch*NLd];
static __device__ float g_lop[SPL][Bb*CLd*NLd];
static __device__ float g_lo1[Bb*CLd*NLd];
static __device__ float g_lo2[Bb*CLd*NLd];
static __device__ float g_zt [Bb*CLd*NLd];
static __device__ float g_mq [Bb*Kch],  g_rq [Bb*Kch];
static __device__ float g_mlv[Bb*CLd],  g_rlv[Bb*CLd];
static __device__ float g_mw [Bb*Vch],  g_rw [Bb*Vch];
static __device__ float g_lmax[Bb*Hh*NLd], g_lsum[Bb*Hh*NLd];

__device__ __forceinline__ float gelu_f(float x){
    return 0.5f*x*(1.0f + erff(x*0.70710678118654752f));
}

// ---------------- HMMA GEMM: C[M,N] = act(A[M,K] @ W[N,K]^T + b) ----------------
// mma.sync m16n8k16 bf16, 3-pass hi/lo split. CTA 128x128, BK=32, 8 warps m32xn64.
// Software-pipelined: global->reg prefetch for iter+1 overlaps compute of iter.
// Optional fused A: A_eff = fv * (A - fm[b]) * fr[b]  (per-channel inorm * elementwise)
#define GP 40

__device__ __forceinline__ void mma16816(float* c, const uint32_t* a, const uint32_t* b){
    asm volatile("mma.sync.aligned.m16n8k16.row.col.f32.bf16.bf16.f32 "
        "{%0,%1,%2,%3}, {%4,%5,%6,%7}, {%8,%9}, {%0,%1,%2,%3};"
        : "+f"(c[0]),"+f"(c[1]),"+f"(c[2]),"+f"(c[3])
        : "r"(a[0]),"r"(a[1]),"r"(a[2]),"r"(a[3]), "r"(b[0]),"r"(b[1]));
}
__device__ __forceinline__ uint32_t bfpack(float x, float y){
    __nv_bfloat162 t; t.x = __float2bfloat16(x); t.y = __float2bfloat16(y);
    return *(uint32_t*)&t;
}

__device__ __forceinline__ void ld_tiles(
    const float* __restrict__ A, const float* __restrict__ Wt, int K,
    int m0, int n0, int k0, int t, float4* pa, float4* pw,
    const float* __restrict__ fv, const float* __restrict__ fm, const float* __restrict__ fr)
{
    #pragma unroll
    for (int i = 0; i < 4; i++){
        int q = t + i * 256, row = q >> 3, kc = (q & 7) << 2;
        float4 a = *(const float4*)(A + (size_t)(m0 + row) * K + k0 + kc);
        if (fv){
            int b = (m0 + row) >> 12;
            float4 vm = *(const float4*)(fm + b * K + k0 + kc);
            float4 vr = *(const float4*)(fr + b * K + k0 + kc);
            float4 vv = *(const float4*)(fv + (size_t)(m0 + row) * K + k0 + kc);
            a.x = vv.x*(a.x - vm.x)*vr.x; a.y = vv.y*(a.y - vm.y)*vr.y;
            a.z = vv.z*(a.z - vm.z)*vr.z; a.w = vv.w*(a.w - vm.w)*vr.w;
        }
        pa[i] = a;
        pw[i] = *(const float4*)(Wt + (size_t)(n0 + row) * K + k0 + kc);
    }
}

__global__ __launch_bounds__(256) void tc_gemm(
    const float* __restrict__ A, const float* __restrict__ Wt,
    const float* __restrict__ bias, float* __restrict__ C,
    int N, int K, int act,
    const float* __restrict__ fv, const float* __restrict__ fm, const float* __restrict__ fr)
{
    __shared__ __nv_bfloat16 sA[2][128*GP];
    __shared__ __nv_bfloat16 sW[2][128*GP];

    const int t = threadIdx.x, lane = t & 31, wid = t >> 5;
    const int m0 = blockIdx.y * 128, n0 = blockIdx.x * 128;
    const int wm = (wid & 3) * 32, wn = (wid >> 2) * 64;
    const int fr_ = lane >> 2, fc = (lane & 3) * 2;

    float acc[2][8][4];
    #pragma unroll
    for (int i=0;i<2;i++)
        #pragma unroll
        for (int j=0;j<8;j++){ acc[i][j][0]=0.f; acc[i][j][1]=0.f; acc[i][j][2]=0.f; acc[i][j][3]=0.f; }

    float4 pa[4], pw[4];
    ld_tiles(A, Wt, K, m0, n0, 0, t, pa, pw, fv, fm, fr);

    const int niter = K >> 5;
    for (int it = 0; it < niter; it++){
        // convert staged regs -> smem hi/lo
        #pragma unroll
        for (int i = 0; i < 4; i++){
            int q = t + i * 256;
            int row = q >> 3, kc = (q & 7) << 2;
            float4 a = pa[i], w = pw[i];
            uint32_t off = row * GP + kc;
            float hx = __bfloat162float(__float2bfloat16(a.x));
            float hy = __bfloat162float(__float2bfloat16(a.y));
            float hz = __bfloat162float(__float2bfloat16(a.z));
            float hw = __bfloat162float(__float2bfloat16(a.w));
            *(uint32_t*)&sA[0][off]     = bfpack(a.x, a.y);
            *(uint32_t*)&sA[0][off + 2] = bfpack(a.z, a.w);
            *(uint32_t*)&sA[1][off]     = bfpack(a.x - hx, a.y - hy);
            *(uint32_t*)&sA[1][off + 2] = bfpack(a.z - hz, a.w - hw);
            float gx = __bfloat162float(__float2bfloat16(w.x));
            float gy = __bfloat162float(__float2bfloat16(w.y));
            float gz = __bfloat162float(__float2bfloat16(w.z));
            float gw = __bfloat162float(__float2bfloat16(w.w));
            *(uint32_t*)&sW[0][off]     = bfpack(w.x, w.y);
            *(uint32_t*)&sW[0][off + 2] = bfpack(w.z, w.w);
            *(uint32_t*)&sW[1][off]     = bfpack(w.x - gx, w.y - gy);
            *(uint32_t*)&sW[1][off + 2] = bfpack(w.z - gz, w.w - gw);
        }
        __syncthreads();
        if (it + 1 < niter)
            ld_tiles(A, Wt, K, m0, n0, (it + 1) << 5, t, pa, pw, fv, fm, fr);

        #pragma unroll
        for (int ks = 0; ks < 2; ks++){
            const int kk = ks * 16;
            uint32_t ah[2][4], al[2][4];
            #pragma unroll
            for (int mi = 0; mi < 2; mi++){
                int r = wm + mi * 16 + fr_;
                ah[mi][0] = *(const uint32_t*)&sA[0][(r    ) * GP + kk + fc];
                ah[mi][1] = *(const uint32_t*)&sA[0][(r + 8) * GP + kk + fc];
                ah[mi][2] = *(const uint32_t*)&sA[0][(r    ) * GP + kk + fc + 8];
                ah[mi][3] = *(const uint32_t*)&sA[0][(r + 8) * GP + kk + fc + 8];
                al[mi][0] = *(const uint32_t*)&sA[1][(r    ) * GP + kk + fc];
                al[mi][1] = *(const uint32_t*)&sA[1][(r + 8) * GP + kk + fc];
                al[mi][2] = *(const uint32_t*)&sA[1][(r    ) * GP + kk + fc + 8];
                al[mi][3] = *(const uint32_t*)&sA[1][(r + 8) * GP + kk + fc + 8];
            }
            uint32_t bh[8][2], bl[8][2];
            #pragma unroll
            for (int ni = 0; ni < 8; ni++){
                int n = wn + ni * 8 + fr_;
                bh[ni][0] = *(const uint32_t*)&sW[0][n * GP + kk + fc];
                bh[ni][1] = *(const uint32_t*)&sW[0][n * GP + kk + fc + 8];
                bl[ni][0] = *(const uint32_t*)&sW[1][n * GP + kk + fc];
                bl[ni][1] = *(const uint32_t*)&sW[1][n * GP + kk + fc + 8];
            }
            #pragma unroll
            for (int mi = 0; mi < 2; mi++)
                #pragma unroll
                for (int ni = 0; ni < 8; ni++){
                    mma16816(acc[mi][ni], ah[mi], bh[ni]);
                    mma16816(acc[mi][ni], ah[mi], bl[ni]);
                    mma16816(acc[mi][ni], al[mi], bh[ni]);
                }
        }
        __syncthreads();
    }

    #pragma unroll
    for (int mi = 0; mi < 2; mi++){
        #pragma unroll
        for (int ni = 0; ni < 8; ni++){
            int m = m0 + wm + mi * 16 + fr_;
            int n = n0 + wn + ni * 8 + fc;
            float b0 = bias[n], b1 = bias[n + 1];
            float v0 = acc[mi][ni][0] + b0, v1 = acc[mi][ni][1] + b1;
            float v2 = acc[mi][ni][2] + b0, v3 = acc[mi][ni][3] + b1;
            if (act){ v0 = gelu_f(v0); v1 = gelu_f(v1); v2 = gelu_f(v2); v3 = gelu_f(v3); }
            *(float2*)&C[(size_t)m * N + n]       = make_float2(v0, v1);
            *(float2*)&C[(size_t)(m + 8) * N + n] = make_float2(v2, v3);
        }
    }
}

// ---------------- per-(b,c) mean/rstd over HW (fp32) ----------------
__global__ void stats_kernel(const float* __restrict__ A, float* __restrict__ mean,
                             float* __restrict__ rstd, int C)
{
    const int b = blockIdx.y, c = blockIdx.x*32 + threadIdx.x, ty = threadIdx.y;
    const float* base = A + (size_t)b*HWd*C + c;
    float s=0.f, s2=0.f;
    for (int hw=ty; hw<HWd; hw+=16){ float v = base[(size_t)hw*C]; s+=v; s2+=v*v; }
    __shared__ float ss[16][33], sq[16][33];
    ss[ty][threadIdx.x]=s; sq[ty][threadIdx.x]=s2;
    __syncthreads();
    if (ty==0){
        #pragma unroll
        for (int i=1;i<16;i++){ s+=ss[i][threadIdx.x]; s2+=sq[i][threadIdx.x]; }
        float m = s*(1.f/HWd), var = s2*(1.f/HWd) - m*m;
        mean[b*C+c]=m; rstd[b*C+c]=rsqrtf(var + 1e-5f);
    }
}

// ---------------- lang 1x1 conv: mode 1 gelu, 2 mask, 4 transpose, 8 inorm(NL) ----
__global__ __launch_bounds__(256) void lang_conv_kernel(
    const float* __restrict__ in, const float* __restrict__ w,
    const float* __restrict__ bias, const float* __restrict__ mask,
    float* __restrict__ out, int Cout, int mode)
{
    __shared__ float in_s[32][33];
    __shared__ float w_s [32][33];
    const int b = blockIdx.x, o0 = blockIdx.y*32, t = threadIdx.x;
    const int n = t & 31, og = t >> 5;
    float acc[4] = {0.f,0.f,0.f,0.f};
    for (int i0 = 0; i0 < CLd; i0 += 32){
        for (int e = t; e < 1024; e += 256) in_s[e>>5][e&31] = in[((size_t)b*CLd + i0+(e>>5))*NLd + (e&31)];
        for (int e = t; e < 1024; e += 256) w_s[e>>5][e&31]  = w[(size_t)(o0+(e>>5))*CLd + i0+(e&31)];
        __syncthreads();
        #pragma unroll
        for (int ii = 0; ii < 32; ii++){
            float iv = in_s[ii][n];
            acc[0]+=w_s[og   ][ii]*iv; acc[1]+=w_s[og+ 8][ii]*iv;
            acc[2]+=w_s[og+16][ii]*iv; acc[3]+=w_s[og+24][ii]*iv;
        }
        __syncthreads();
    }
    float mv = (mode & 2) ? mask[b*NLd + n] : 1.f;
    #pragma unroll
    for (int j = 0; j < 4; j++){
        int o = o0 + og + 8*j;
        float v = acc[j] + bias[o];
        if (mode & 2) v *= mv;
        if (mode & 8){
            float s=v, s2=v*v;
            #pragma unroll
            for (int off=16;off;off>>=1){ s+=__shfl_xor_sync(~0u,s,off); s2+=__shfl_xor_sync(~0u,s2,off); }
            float mn = s*(1.f/32.f), vr = s2*(1.f/32.f) - mn*mn;
            v = (v-mn)*rsqrtf(vr + 1e-5f);
        }
        if (mode & 1) v = gelu_f(v);
        if (mode & 4) out[((size_t)b*NLd + n)*Cout + o] = v;
        else          out[((size_t)b*Cout + o)*NLd + n] = v;
    }
}

// ---------------- sim = inorm(q).k * scale + 1e4*mask - 1e4 ----------------
__global__ __launch_bounds__(256) void sim_kernel(const float* __restrict__ mask)
{
    __shared__ float ks[64*32];
    __shared__ float qm[64], qr[64], mk[32];
    __shared__ float qrow[8][64];
    const int bh = blockIdx.y, b = bh>>3, h = bh&7;
    const int t = threadIdx.x, w = t>>5, lane = t&31;
    for (int e = t; e < 2048; e += 256) ks[e] = g_k[((size_t)b*Kch + h*64)*NLd + e];
    if (t < 64){ qm[t]=g_mq[b*Kch+h*64+t]; qr[t]=g_rq[b*Kch+h*64+t]; }
    if (t >= 64 && t < 96) mk[t-64]=mask[b*NLd+t-64];
    __syncthreads();
    const int hw0 = blockIdx.x*1024;
    for (int it = 0; it < 128; it++){
        int hw = hw0 + it*8 + w;
        const float2 q2 = ((const float2*)&g_q[((size_t)(b*HWd+hw))*Kch + h*64])[lane];
        qrow[w][2*lane  ] = (q2.x - qm[2*lane  ])*qr[2*lane  ];
        qrow[w][2*lane+1] = (q2.y - qm[2*lane+1])*qr[2*lane+1];
        __syncwarp();
        float acc = 0.f;
        #pragma unroll 16
        for (int d = 0; d < 64; d++) acc += qrow[w][d]*ks[d*32+lane];
        g_sim[((size_t)bh*HWd+hw)*32+lane] =
            acc*0.044194173824159216f + 10000.f*mk[lane] - 10000.f;
        __syncwarp();
    }
}

// ---------------- lang->image softmax stats over HW ----------------
__global__ void latt_stats_kernel()
{
    const int bh = blockIdx.x, n = threadIdx.x, ty = threadIdx.y;
    float m = -1e30f, s = 0.f;
    for (int hw = ty; hw < HWd; hw += 32){
        float v = g_sim[((size_t)bh*HWd+hw)*32 + n];
        float nm = fmaxf(m, v);
        s = s*__expf(m-nm) + __expf(v-nm); m = nm;
    }
    __shared__ float sm_[32][33], ss[32][33];
    sm_[ty][n]=m; ss[ty][n]=s;
    __syncthreads();
    if (ty == 0){
        for (int i = 1; i < 32; i++){
            float m2=sm_[i][n], s2=ss[i][n], nm=fmaxf(m,m2);
            s = s*__expf(m-nm) + s2*__expf(m2-nm); m = nm;
        }
        g_lmax[bh*32+n]=m; g_lsum[bh*32+n]=s;
    }
}

// ---------------- image->lang: out = softmax_n(sim) . v ----------------
__global__ __launch_bounds__(256) void attout_kernel()
{
    __shared__ float v_s[32*68];
    const int bh=blockIdx.y, b=bh>>3, h=bh&7, t=threadIdx.x;
    for (int e=t;e<2048;e+=256) v_s[(e&31)*68+(e>>5)] = g_v[((size_t)b*Vch + h*64)*NLd + e];
    __syncthreads();
    const int hw = blockIdx.x*256 + t;
    const float4* sp = (const float4*)&g_sim[((size_t)bh*HWd+hw)*32];
    float sv[32];
    #pragma unroll
    for (int j=0;j<8;j++){ float4 s4=sp[j]; sv[4*j]=s4.x; sv[4*j+1]=s4.y; sv[4*j+2]=s4.z; sv[4*j+3]=s4.w; }
    float mx=-1e30f;
    #pragma unroll
    for (int i=0;i<32;i++) mx=fmaxf(mx,sv[i]);
    float sum=0.f;
    #pragma unroll
    for (int i=0;i<32;i++){ sv[i]=__expf(sv[i]-mx); sum+=sv[i]; }
    float inv=1.f/sum;
    float acc[64];
    #pragma unroll
    for (int i=0;i<64;i++) acc[i]=0.f;
    #pragma unroll 4
    for (int n=0;n<32;n++){
        float a = sv[n]*inv;
        const float4* vr = (const float4*)&v_s[n*68];
        #pragma unroll
        for (int j=0;j<16;j++){
            float4 vv = vr[j];
            acc[4*j]+=a*vv.x; acc[4*j+1]+=a*vv.y; acc[4*j+2]+=a*vv.z; acc[4*j+3]+=a*vv.w;
        }
    }
    float4* op = (float4*)&g_att[((size_t)(b*HWd+hw))*Vch + h*64];
    #pragma unroll
    for (int j=0;j<16;j++){ float4 o; o.x=acc[4*j]; o.y=acc[4*j+1]; o.z=acc[4*j+2]; o.w=acc[4*j+3]; op[j]=o; }
}

// ---------------- lang_out partials: latt . inorm(lv) over an HW slice ----------
__global__ __launch_bounds__(256) void langout_part_kernel()
{
    __shared__ float ps[32*32];
    __shared__ float lvs[32*96];
    __shared__ float lmx[32], lsm[32];
    const int bh=blockIdx.x, spl=blockIdx.y, b=bh>>3, h=bh&7, t=threadIdx.x;
    if (t<32){ lmx[t]=g_lmax[bh*32+t]; lsm[t]=1.f/g_lsum[bh*32+t]; }
    __syncthreads();
    const int n=t&31, c0=(t>>5)*12;
    float acc[12];
    #pragma unroll
    for (int j=0;j<12;j++) acc[j]=0.f;
    const int hwA = spl*(HWd/SPL), hwB = hwA + HWd/SPL;
    for (int hw0=hwA; hw0<hwB; hw0+=32){
        for (int e=t;e<1024;e+=256){
            int r=e>>5, nn=e&31;
            ps[e]=__expf(g_sim[((size_t)bh*HWd+hw0+r)*32+nn]-lmx[nn])*lsm[nn];
        }
        for (int e=t;e<3072;e+=256){
            int r=e/96, cc=e-r*96, ch=h*96+cc;
            lvs[e]=(g_lv[((size_t)(b*HWd+hw0+r))*CLd+ch]-g_mlv[b*CLd+ch])*g_rlv[b*CLd+ch];
        }
        __syncthreads();
        #pragma unroll 8
        for (int r=0;r<32;r++){
            float p=ps[r*32+n];
            #pragma unroll
            for (int j=0;j<12;j++) acc[j]+=p*lvs[r*96+c0+j];
        }
        __syncthreads();
    }
    #pragma unroll
    for (int j=0;j<12;j++)
        g_lop[spl][((size_t)b*CLd + h*96+c0+j)*NLd + n] = acc[j];
}

// ---------------- reduce partials + mask -> g_lo1 ----------------
__global__ void lo1_reduce_kernel(const float* __restrict__ mask)
{
    const int idx = blockIdx.x*256 + threadIdx.x;
    float s = 0.f;
    #pragma unroll
    for (int p = 0; p < SPL; p++) s += g_lop[p][idx];
    int n = idx & 31, b = idx / (CLd*NLd);
    g_lo1[idx] = s * mask[b*NLd + n];
}

// ---------------- elementwise: zt = lang * lang_out2 ----------------
__global__ void ztmul_kernel()
{
    size_t i = ((size_t)blockIdx.x*256 + threadIdx.x)*4;
    float4 a = *(const float4*)&g_lang[i];
    float4 b4 = *(const float4*)&g_lo2[i];
    float4 r; r.x=a.x*b4.x; r.y=a.y*b4.y; r.z=a.z*b4.z; r.w=a.w*b4.w;
    *(float4*)&g_zt[i] = r;
}

extern "C" void kernel_launch(void* const* d_in, const int* in_sizes, int n_in,
                              void* d_out, int out_size)
{
    const float* x      = (const float*)d_in[0];
    const float* l      = (const float*)d_in[1];
    const float* lmask  = (const float*)d_in[2];
    const float* w_vis  = (const float*)d_in[3];  const float* b_vis  = (const float*)d_in[4];
    const float* w_langp= (const float*)d_in[5];  const float* b_langp= (const float*)d_in[6];
    const float* w_q    = (const float*)d_in[7];  const float* b_q    = (const float*)d_in[8];
    const float* w_k    = (const float*)d_in[9];  const float* b_k    = (const float*)d_in[10];
    const float* w_v    = (const float*)d_in[11]; const float* b_v    = (const float*)d_in[12];
    const float* w_lv   = (const float*)d_in[13]; const float* b_lv   = (const float*)d_in[14];
    const float* w_W    = (const float*)d_in[15]; const float* b_W    = (const float*)d_in[16];
    const float* w_langW= (const float*)d_in[17]; const float* b_langW= (const float*)d_in[18];
    const float* w_mm   = (const float*)d_in[19]; const float* b_mm   = (const float*)d_in[20];
    const float* w_langmm=(const float*)d_in[21]; const float* b_langmm=(const float*)d_in[22];
    float* out = (float*)d_out;

    float *p_vis, *p_q, *p_lv, *p_att, *p_vo, *p_lang, *p_k, *p_v, *p_lo1, *p_lo2, *p_zt;
    float *p_mq, *p_rq, *p_mlv, *p_rlv, *p_mw, *p_rw;
    cudaGetSymbolAddress((void**)&p_vis, g_vis);  cudaGetSymbolAddress((void**)&p_q,  g_q);
    cudaGetSymbolAddress((void**)&p_lv,  g_lv);   cudaGetSymbolAddress((void**)&p_att,g_att);
    cudaGetSymbolAddress((void**)&p_vo,  g_vo);
    cudaGetSymbolAddress((void**)&p_lang,g_lang); cudaGetSymbolAddress((void**)&p_k,  g_k);
    cudaGetSymbolAddress((void**)&p_v,   g_v);    cudaGetSymbolAddress((void**)&p_lo1,g_lo1);
    cudaGetSymbolAddress((void**)&p_lo2, g_lo2);  cudaGetSymbolAddress((void**)&p_zt, g_zt);
    cudaGetSymbolAddress((void**)&p_mq,  g_mq);   cudaGetSymbolAddress((void**)&p_rq, g_rq);
    cudaGetSymbolAddress((void**)&p_mlv, g_mlv);  cudaGetSymbolAddress((void**)&p_rlv,g_rlv);
    cudaGetSymbolAddress((void**)&p_mw,  g_mw);   cudaGetSymbolAddress((void**)&p_rw, g_rw);

    dim3 blk256(256);
    // big GEMMs (HMMA bf16 3-pass split, pipelined)
    tc_gemm<<<dim3(Dd/128,  Mm/128), blk256>>>(x, w_vis, b_vis, p_vis, Dd,  Dd, 1, 0, 0, 0);
    tc_gemm<<<dim3(Kch/128, Mm/128), blk256>>>(x, w_q,   b_q,   p_q,   Kch, Dd, 0, 0, 0, 0);
    tc_gemm<<<dim3(CLd/128, Mm/128), blk256>>>(x, w_lv,  b_lv,  p_lv,  CLd, Dd, 0, 0, 0, 0);
    stats_kernel<<<dim3(Kch/32, Bb), dim3(32,16)>>>(p_q,  p_mq,  p_rq,  Kch);
    stats_kernel<<<dim3(CLd/32, Bb), dim3(32,16)>>>(p_lv, p_mlv, p_rlv, CLd);
    // lang-side convs
    lang_conv_kernel<<<dim3(Bb, CLd/32), blk256>>>(l, w_langp, b_langp, lmask, p_lang, CLd, 1);
    lang_conv_kernel<<<dim3(Bb, Kch/32), blk256>>>(l, w_k, b_k, lmask, p_k, Kch, 2);
    lang_conv_kernel<<<dim3(Bb, Vch/32), blk256>>>(l, w_v, b_v, lmask, p_v, Vch, 2);
    // attention
    sim_kernel<<<dim3(HWd/1024, Bb*Hh), blk256>>>(lmask);
    latt_stats_kernel<<<Bb*Hh, dim3(32,32)>>>();
    attout_kernel<<<dim3(HWd/256, Bb*Hh), blk256>>>();
    langout_part_kernel<<<dim3(Bb*Hh, SPL), blk256>>>();
    lo1_reduce_kernel<<<(Bb*CLd*NLd)/256, blk256>>>(lmask);
    // lang_out2 = inorm(conv(lang_out, w_langW))
    lang_conv_kernel<<<dim3(Bb, CLd/32), blk256>>>(p_lo1, w_langW, b_langW, lmask, p_lo2, CLd, 8);
    // vis_out = inorm(conv(att_out, w_W))
    tc_gemm<<<dim3(Vch/128, Mm/128), blk256>>>(p_att, w_W, b_W, p_vo, Vch, Vch, 0, 0, 0, 0);
    stats_kernel<<<dim3(Vch/32, Bb), dim3(32,16)>>>(p_vo, p_mw, p_rw, Vch);
    // mm = gelu(conv(vis * inorm(vo), w_mm)) -> out[0 : M*V]   (zmul fused into A-staging)
    tc_gemm<<<dim3(Vch/128, Mm/128), blk256>>>(p_vo, w_mm, b_mm, out, Vch, Vch, 1, p_vis, p_mw, p_rw);
    // lang_mm = gelu(conv(lang*lo2, w_langmm)) transposed -> out tail
    ztmul_kernel<<<(Bb*CLd*NLd)/1024, blk256>>>();
    lang_conv_kernel<<<dim3(Bb, CLd/32), blk256>>>(p_zt, w_langmm, b_langmm, lmask,
                                                   out + (size_t)Mm*Vch, CLd, 1|4);
    (void)in_sizes; (void)n_in; (void)out_size;
}

// round 8
// speedup vs baseline: 1.8269x; 1.4619x over previous
#include <cuda_runtime.h>
#include <cuda_bf16.h>
#include <math.h>
#include <stdint.h>

#define Bb   16
#define HWd  4096
#define Dd   512
#define CLd  768
#define Kch  512
#define Vch  512
#define NLd  32
#define Hh   8
#define Mm   (Bb*HWd)
#define SPL  8

// ---------------- scratch ----------------
static __device__ float g_vis[(size_t)Mm*Dd];
static __device__ float g_q  [(size_t)Mm*Kch];
static __device__ float g_lv [(size_t)Mm*CLd];
static __device__ float g_vo [(size_t)Mm*Vch];
static __device__ float g_sim[(size_t)Bb*Hh*HWd*NLd];
static __device__ __nv_bfloat16 g_xh[(size_t)Mm*Dd],  g_xl[(size_t)Mm*Dd];
static __device__ __nv_bfloat16 g_ath[(size_t)Mm*Vch], g_atl[(size_t)Mm*Vch];
static __device__ __nv_bfloat16 g_zh[(size_t)Mm*Vch],  g_zl[(size_t)Mm*Vch];
#define WOFF_VIS 0
#define WOFF_Q   262144
#define WOFF_LV  524288
#define WOFF_W   917504
#define WOFF_MM  1179648
static __device__ __nv_bfloat16 g_wh[1441792], g_wl[1441792];
static __device__ float g_lang[Bb*CLd*NLd];
static __device__ float g_k  [Bb*Kch*NLd];
static __device__ float g_v  [Bb*Vch*NLd];
static __device__ float g_lop[SPL][Bb*CLd*NLd];
static __device__ float g_lo1[Bb*CLd*NLd];
static __device__ float g_lo2[Bb*CLd*NLd];
static __device__ float g_zt [Bb*CLd*NLd];
static __device__ float g_mq [Bb*Kch],  g_rq [Bb*Kch];
static __device__ float g_mlv[Bb*CLd],  g_rlv[Bb*CLd];
static __device__ float g_mw [Bb*Vch],  g_rw [Bb*Vch];
static __device__ float g_lmax[Bb*Hh*NLd], g_lsum[Bb*Hh*NLd];

__device__ __forceinline__ float gelu_f(float x){
    return 0.5f*x*(1.0f + erff(x*0.70710678118654752f));
}
__device__ __forceinline__ uint32_t smem_u32(const void* p){
    uint32_t a;
    asm("{ .reg .u64 t; cvta.to.shared.u64 t, %1; cvt.u32.u64 %0, t; }" : "=r"(a) : "l"(p));
    return a;
}
__device__ __forceinline__ void cp16(uint32_t s, const void* g){
    asm volatile("cp.async.cg.shared.global [%0], [%1], 16;" :: "r"(s), "l"(g));
}
__device__ __forceinline__ void mma16816(float* c, const uint32_t* a, const uint32_t* b){
    asm volatile("mma.sync.aligned.m16n8k16.row.col.f32.bf16.bf16.f32 "
        "{%0,%1,%2,%3}, {%4,%5,%6,%7}, {%8,%9}, {%0,%1,%2,%3};"
        : "+f"(c[0]),"+f"(c[1]),"+f"(c[2]),"+f"(c[3])
        : "r"(a[0]),"r"(a[1]),"r"(a[2]),"r"(a[3]), "r"(b[0]),"r"(b[1]));
}

// ---------------- fp32 -> bf16 hi/lo split ----------------
__global__ void cvt_split(const float* __restrict__ src,
                          __nv_bfloat16* __restrict__ hi, __nv_bfloat16* __restrict__ lo)
{
    size_t i = ((size_t)blockIdx.x*256 + threadIdx.x)*4;
    float4 v = *(const float4*)(src + i);
    __nv_bfloat16 h0=__float2bfloat16(v.x), h1=__float2bfloat16(v.y);
    __nv_bfloat16 h2=__float2bfloat16(v.z), h3=__float2bfloat16(v.w);
    __nv_bfloat162 hp0; hp0.x=h0; hp0.y=h1;
    __nv_bfloat162 hp1; hp1.x=h2; hp1.y=h3;
    *(uint2*)(hi+i) = make_uint2(*(uint32_t*)&hp0, *(uint32_t*)&hp1);
    __nv_bfloat162 lp0, lp1;
    lp0.x=__float2bfloat16(v.x-__bfloat162float(h0)); lp0.y=__float2bfloat16(v.y-__bfloat162float(h1));
    lp1.x=__float2bfloat16(v.z-__bfloat162float(h2)); lp1.y=__float2bfloat16(v.w-__bfloat162float(h3));
    *(uint2*)(lo+i) = make_uint2(*(uint32_t*)&lp0, *(uint32_t*)&lp1);
}

// ---------------- multistage HMMA GEMM (bf16 hi/lo inputs) ----------------
// C[M,N] = act(A @ W^T + b); CTA 128x128, BK=32, 3-stage cp.async pipeline.
#define GP 40
#define BUFB 10240              /* 128*GP*2 */
#define STGB (4*BUFB)           /* per-stage: Ah,Al,Wh,Wl */
#define NSTG 3
#define SMEMB (NSTG*STGB)

__device__ __forceinline__ void issue_stage(
    uint32_t sb, const __nv_bfloat16* Ah, const __nv_bfloat16* Al,
    const __nv_bfloat16* Wh, const __nv_bfloat16* Wl,
    int K, int m0, int n0, int k0, int t)
{
    #pragma unroll
    for (int i = 0; i < 2; i++){
        int q = t + i*256;
        int row = q >> 2, seg = q & 3;
        uint32_t so = row*80 + seg*16;
        size_t ga = (size_t)(m0+row)*K + k0 + seg*8;
        size_t gw = (size_t)(n0+row)*K + k0 + seg*8;
        cp16(sb + so,          Ah + ga);
        cp16(sb + BUFB + so,   Al + ga);
        cp16(sb + 2*BUFB + so, Wh + gw);
        cp16(sb + 3*BUFB + so, Wl + gw);
    }
}

__global__ __launch_bounds__(256) void tc_gemm(
    const __nv_bfloat16* __restrict__ Ah, const __nv_bfloat16* __restrict__ Al,
    const __nv_bfloat16* __restrict__ Wh, const __nv_bfloat16* __restrict__ Wl,
    const float* __restrict__ bias, float* __restrict__ C, int N, int K, int act)
{
    extern __shared__ char sm[];
    const uint32_t smb = smem_u32(sm);
    const int t = threadIdx.x, lane = t & 31, wid = t >> 5;
    const int m0 = blockIdx.y * 128, n0 = blockIdx.x * 128;
    const int wm = (wid & 3) * 32, wn = (wid >> 2) * 64;
    const int fr_ = lane >> 2, fc = (lane & 3) * 2;

    float acc[2][8][4];
    #pragma unroll
    for (int i=0;i<2;i++)
        #pragma unroll
        for (int j=0;j<8;j++){ acc[i][j][0]=0.f; acc[i][j][1]=0.f; acc[i][j][2]=0.f; acc[i][j][3]=0.f; }

    const int niter = K >> 5;
    #pragma unroll
    for (int s = 0; s < NSTG-1; s++){
        issue_stage(smb + s*STGB, Ah, Al, Wh, Wl, K, m0, n0, s<<5, t);
        asm volatile("cp.async.commit_group;");
    }

    for (int it = 0; it < niter; it++){
        asm volatile("cp.async.wait_group 1;");
        __syncthreads();
        int nxt = it + NSTG - 1;
        if (nxt < niter)
            issue_stage(smb + (nxt%NSTG)*STGB, Ah, Al, Wh, Wl, K, m0, n0, nxt<<5, t);
        asm volatile("cp.async.commit_group;");

        const char* sb = sm + (it%NSTG)*STGB;
        const char* sa_h = sb;
        const char* sa_l = sb + BUFB;
        const char* sw_h = sb + 2*BUFB;
        const char* sw_l = sb + 3*BUFB;

        #pragma unroll
        for (int ks = 0; ks < 2; ks++){
            const int kk = ks * 16;
            uint32_t ah[2][4], al[2][4];
            #pragma unroll
            for (int mi = 0; mi < 2; mi++){
                int r = wm + mi * 16 + fr_;
                ah[mi][0] = *(const uint32_t*)(sa_h + (r    )*80 + (kk+fc)*2);
                ah[mi][1] = *(const uint32_t*)(sa_h + (r + 8)*80 + (kk+fc)*2);
                ah[mi][2] = *(const uint32_t*)(sa_h + (r    )*80 + (kk+fc+8)*2);
                ah[mi][3] = *(const uint32_t*)(sa_h + (r + 8)*80 + (kk+fc+8)*2);
                al[mi][0] = *(const uint32_t*)(sa_l + (r    )*80 + (kk+fc)*2);
                al[mi][1] = *(const uint32_t*)(sa_l + (r + 8)*80 + (kk+fc)*2);
                al[mi][2] = *(const uint32_t*)(sa_l + (r    )*80 + (kk+fc+8)*2);
                al[mi][3] = *(const uint32_t*)(sa_l + (r + 8)*80 + (kk+fc+8)*2);
            }
            uint32_t bh[8][2], bl[8][2];
            #pragma unroll
            for (int ni = 0; ni < 8; ni++){
                int n = wn + ni * 8 + fr_;
                bh[ni][0] = *(const uint32_t*)(sw_h + n*80 + (kk+fc)*2);
                bh[ni][1] = *(const uint32_t*)(sw_h + n*80 + (kk+fc+8)*2);
                bl[ni][0] = *(const uint32_t*)(sw_l + n*80 + (kk+fc)*2);
                bl[ni][1] = *(const uint32_t*)(sw_l + n*80 + (kk+fc+8)*2);
            }
            #pragma unroll
            for (int mi = 0; mi < 2; mi++)
                #pragma unroll
                for (int ni = 0; ni < 8; ni++){
                    mma16816(acc[mi][ni], ah[mi], bh[ni]);
                    mma16816(acc[mi][ni], ah[mi], bl[ni]);
                    mma16816(acc[mi][ni], al[mi], bh[ni]);
                }
        }
        __syncthreads();
    }

    #pragma unroll
    for (int mi = 0; mi < 2; mi++){
        #pragma unroll
        for (int ni = 0; ni < 8; ni++){
            int m = m0 + wm + mi * 16 + fr_;
            int n = n0 + wn + ni * 8 + fc;
            float b0 = bias[n], b1 = bias[n + 1];
            float v0 = acc[mi][ni][0] + b0, v1 = acc[mi][ni][1] + b1;
            float v2 = acc[mi][ni][2] + b0, v3 = acc[mi][ni][3] + b1;
            if (act){ v0 = gelu_f(v0); v1 = gelu_f(v1); v2 = gelu_f(v2); v3 = gelu_f(v3); }
            *(float2*)&C[(size_t)m * N + n]       = make_float2(v0, v1);
            *(float2*)&C[(size_t)(m + 8) * N + n] = make_float2(v2, v3);
        }
    }
}

// ---------------- per-(b,c) mean/rstd over HW (fp32) ----------------
__global__ void stats_kernel(const float* __restrict__ A, float* __restrict__ mean,
                             float* __restrict__ rstd, int C)
{
    const int b = blockIdx.y, c = blockIdx.x*32 + threadIdx.x, ty = threadIdx.y;
    const float* base = A + (size_t)b*HWd*C + c;
    float s=0.f, s2=0.f;
    for (int hw=ty; hw<HWd; hw+=16){ float v = base[(size_t)hw*C]; s+=v; s2+=v*v; }
    __shared__ float ss[16][33], sq[16][33];
    ss[ty][threadIdx.x]=s; sq[ty][threadIdx.x]=s2;
    __syncthreads();
    if (ty==0){
        #pragma unroll
        for (int i=1;i<16;i++){ s+=ss[i][threadIdx.x]; s2+=sq[i][threadIdx.x]; }
        float m = s*(1.f/HWd), var = s2*(1.f/HWd) - m*m;
        mean[b*C+c]=m; rstd[b*C+c]=rsqrtf(var + 1e-5f);
    }
}

// ---------------- lang 1x1 conv: mode 1 gelu, 2 mask, 4 transpose, 8 inorm(NL) ----
__global__ __launch_bounds__(256) void lang_conv_kernel(
    const float* __restrict__ in, const float* __restrict__ w,
    const float* __restrict__ bias, const float* __restrict__ mask,
    float* __restrict__ out, int Cout, int mode)
{
    __shared__ float in_s[32][33];
    __shared__ float w_s [32][33];
    const int b = blockIdx.x, o0 = blockIdx.y*32, t = threadIdx.x;
    const int n = t & 31, og = t >> 5;
    float acc[4] = {0.f,0.f,0.f,0.f};
    for (int i0 = 0; i0 < CLd; i0 += 32){
        for (int e = t; e < 1024; e += 256) in_s[e>>5][e&31] = in[((size_t)b*CLd + i0+(e>>5))*NLd + (e&31)];
        for (int e = t; e < 1024; e += 256) w_s[e>>5][e&31]  = w[(size_t)(o0+(e>>5))*CLd + i0+(e&31)];
        __syncthreads();
        #pragma unroll
        for (int ii = 0; ii < 32; ii++){
            float iv = in_s[ii][n];
            acc[0]+=w_s[og   ][ii]*iv; acc[1]+=w_s[og+ 8][ii]*iv;
            acc[2]+=w_s[og+16][ii]*iv; acc[3]+=w_s[og+24][ii]*iv;
        }
        __syncthreads();
    }
    float mv = (mode & 2) ? mask[b*NLd + n] : 1.f;
    #pragma unroll
    for (int j = 0; j < 4; j++){
        int o = o0 + og + 8*j;
        float v = acc[j] + bias[o];
        if (mode & 2) v *= mv;
        if (mode & 8){
            float s=v, s2=v*v;
            #pragma unroll
            for (int off=16;off;off>>=1){ s+=__shfl_xor_sync(~0u,s,off); s2+=__shfl_xor_sync(~0u,s2,off); }
            float mn = s*(1.f/32.f), vr = s2*(1.f/32.f) - mn*mn;
            v = (v-mn)*rsqrtf(vr + 1e-5f);
        }
        if (mode & 1) v = gelu_f(v);
        if (mode & 4) out[((size_t)b*NLd + n)*Cout + o] = v;
        else          out[((size_t)b*Cout + o)*NLd + n] = v;
    }
}

// ---------------- sim = inorm(q).k * scale + 1e4*mask - 1e4 ----------------
__global__ __launch_bounds__(256) void sim_kernel(const float* __restrict__ mask)
{
    __shared__ float ks[64*32];
    __shared__ float qm[64], qr[64], mk[32];
    __shared__ float qrow[8][64];
    const int bh = blockIdx.y, b = bh>>3, h = bh&7;
    const int t = threadIdx.x, w = t>>5, lane = t&31;
    for (int e = t; e < 2048; e += 256) ks[e] = g_k[((size_t)b*Kch + h*64)*NLd + e];
    if (t < 64){ qm[t]=g_mq[b*Kch+h*64+t]; qr[t]=g_rq[b*Kch+h*64+t]; }
    if (t >= 64 && t < 96) mk[t-64]=mask[b*NLd+t-64];
    __syncthreads();
    const int hw0 = blockIdx.x*1024;
    for (int it = 0; it < 128; it++){
        int hw = hw0 + it*8 + w;
        const float2 q2 = ((const float2*)&g_q[((size_t)(b*HWd+hw))*Kch + h*64])[lane];
        qrow[w][2*lane  ] = (q2.x - qm[2*lane  ])*qr[2*lane  ];
        qrow[w][2*lane+1] = (q2.y - qm[2*lane+1])*qr[2*lane+1];
        __syncwarp();
        float acc = 0.f;
        #pragma unroll 16
        for (int d = 0; d < 64; d++) acc += qrow[w][d]*ks[d*32+lane];
        g_sim[((size_t)bh*HWd+hw)*32+lane] =
            acc*0.044194173824159216f + 10000.f*mk[lane] - 10000.f;
        __syncwarp();
    }
}

// ---------------- lang->image softmax stats over HW ----------------
__global__ void latt_stats_kernel()
{
    const int bh = blockIdx.x, n = threadIdx.x, ty = threadIdx.y;
    float m = -1e30f, s = 0.f;
    for (int hw = ty; hw < HWd; hw += 32){
        float v = g_sim[((size_t)bh*HWd+hw)*32 + n];
        float nm = fmaxf(m, v);
        s = s*__expf(m-nm) + __expf(v-nm); m = nm;
    }
    __shared__ float sm_[32][33], ss[32][33];
    sm_[ty][n]=m; ss[ty][n]=s;
    __syncthreads();
    if (ty == 0){
        for (int i = 1; i < 32; i++){
            float m2=sm_[i][n], s2=ss[i][n], nm=fmaxf(m,m2);
            s = s*__expf(m-nm) + s2*__expf(m2-nm); m = nm;
        }
        g_lmax[bh*32+n]=m; g_lsum[bh*32+n]=s;
    }
}

// ---------------- image->lang: att_out = softmax_n(sim) . v  (bf16 hi/lo out) ----
__global__ __launch_bounds__(256) void attout_kernel()
{
    __shared__ float v_s[32*68];
    const int bh=blockIdx.y, b=bh>>3, h=bh&7, t=threadIdx.x;
    for (int e=t;e<2048;e+=256) v_s[(e&31)*68+(e>>5)] = g_v[((size_t)b*Vch + h*64)*NLd + e];
    __syncthreads();
    const int hw = blockIdx.x*256 + t;
    const float4* sp = (const float4*)&g_sim[((size_t)bh*HWd+hw)*32];
    float sv[32];
    #pragma unroll
    for (int j=0;j<8;j++){ float4 s4=sp[j]; sv[4*j]=s4.x; sv[4*j+1]=s4.y; sv[4*j+2]=s4.z; sv[4*j+3]=s4.w; }
    float mx=-1e30f;
    #pragma unroll
    for (int i=0;i<32;i++) mx=fmaxf(mx,sv[i]);
    float sum=0.f;
    #pragma unroll
    for (int i=0;i<32;i++){ sv[i]=__expf(sv[i]-mx); sum+=sv[i]; }
    float inv=1.f/sum;
    float acc[64];
    #pragma unroll
    for (int i=0;i<64;i++) acc[i]=0.f;
    #pragma unroll 4
    for (int n=0;n<32;n++){
        float a = sv[n]*inv;
        const float4* vr = (const float4*)&v_s[n*68];
        #pragma unroll
        for (int j=0;j<16;j++){
            float4 vv = vr[j];
            acc[4*j]+=a*vv.x; acc[4*j+1]+=a*vv.y; acc[4*j+2]+=a*vv.z; acc[4*j+3]+=a*vv.w;
        }
    }
    size_t base = (size_t)(b*HWd+hw)*Vch + h*64;
    #pragma unroll
    for (int j=0;j<16;j++){
        __nv_bfloat162 hp, lp;
        float a0=acc[4*j], a1=acc[4*j+1], a2=acc[4*j+2], a3=acc[4*j+3];
        hp.x=__float2bfloat16(a0); hp.y=__float2bfloat16(a1);
        lp.x=__float2bfloat16(a0-__bfloat162float(hp.x)); lp.y=__float2bfloat16(a1-__bfloat162float(hp.y));
        __nv_bfloat162 hq, lq;
        hq.x=__float2bfloat16(a2); hq.y=__float2bfloat16(a3);
        lq.x=__float2bfloat16(a2-__bfloat162float(hq.x)); lq.y=__float2bfloat16(a3-__bfloat162float(hq.y));
        *(uint2*)(g_ath+base+4*j) = make_uint2(*(uint32_t*)&hp, *(uint32_t*)&hq);
        *(uint2*)(g_atl+base+4*j) = make_uint2(*(uint32_t*)&lp, *(uint32_t*)&lq);
    }
}

// ---------------- lang_out partials: latt . inorm(lv) over an HW slice ----------
__global__ __launch_bounds__(256) void langout_part_kernel()
{
    __shared__ float ps[32*32];
    __shared__ float lvs[32*96];
    __shared__ float lmx[32], lsm[32];
    const int bh=blockIdx.x, spl=blockIdx.y, b=bh>>3, h=bh&7, t=threadIdx.x;
    if (t<32){ lmx[t]=g_lmax[bh*32+t]; lsm[t]=1.f/g_lsum[bh*32+t]; }
    __syncthreads();
    const int n=t&31, c0=(t>>5)*12;
    float acc[12];
    #pragma unroll
    for (int j=0;j<12;j++) acc[j]=0.f;
    const int hwA = spl*(HWd/SPL), hwB = hwA + HWd/SPL;
    for (int hw0=hwA; hw0<hwB; hw0+=32){
        for (int e=t;e<1024;e+=256){
            int r=e>>5, nn=e&31;
            ps[e]=__expf(g_sim[((size_t)bh*HWd+hw0+r)*32+nn]-lmx[nn])*lsm[nn];
        }
        for (int e=t;e<3072;e+=256){
            int r=e/96, cc=e-r*96, ch=h*96+cc;
            lvs[e]=(g_lv[((size_t)(b*HWd+hw0+r))*CLd+ch]-g_mlv[b*CLd+ch])*g_rlv[b*CLd+ch];
        }
        __syncthreads();
        #pragma unroll 8
        for (int r=0;r<32;r++){
            float p=ps[r*32+n];
            #pragma unroll
            for (int j=0;j<12;j++) acc[j]+=p*lvs[r*96+c0+j];
        }
        __syncthreads();
    }
    #pragma unroll
    for (int j=0;j<12;j++)
        g_lop[spl][((size_t)b*CLd + h*96+c0+j)*NLd + n] = acc[j];
}

// ---------------- reduce partials + mask -> g_lo1 ----------------
__global__ void lo1_reduce_kernel(const float* __restrict__ mask)
{
    const int idx = blockIdx.x*256 + threadIdx.x;
    float s = 0.f;
    #pragma unroll
    for (int p = 0; p < SPL; p++) s += g_lop[p][idx];
    int n = idx & 31, b = idx / (CLd*NLd);
    g_lo1[idx] = s * mask[b*NLd + n];
}

// ---------------- z = vis * inorm(vo)  ->  bf16 hi/lo ----------------
__global__ void zmul_kernel()
{
    size_t i = ((size_t)blockIdx.x*256 + threadIdx.x)*4;
    int c = (int)(i & 511);
    int b = (int)((i >> 9) >> 12);
    float4 vi = *(const float4*)&g_vis[i];
    float4 vo = *(const float4*)&g_vo[i];
    float z0 = vi.x*(vo.x-g_mw[b*Vch+c  ])*g_rw[b*Vch+c  ];
    float z1 = vi.y*(vo.y-g_mw[b*Vch+c+1])*g_rw[b*Vch+c+1];
    float z2 = vi.z*(vo.z-g_mw[b*Vch+c+2])*g_rw[b*Vch+c+2];
    float z3 = vi.w*(vo.w-g_mw[b*Vch+c+3])*g_rw[b*Vch+c+3];
    __nv_bfloat162 hp, hq, lp, lq;
    hp.x=__float2bfloat16(z0); hp.y=__float2bfloat16(z1);
    hq.x=__float2bfloat16(z2); hq.y=__float2bfloat16(z3);
    lp.x=__float2bfloat16(z0-__bfloat162float(hp.x)); lp.y=__float2bfloat16(z1-__bfloat162float(hp.y));
    lq.x=__float2bfloat16(z2-__bfloat162float(hq.x)); lq.y=__float2bfloat16(z3-__bfloat162float(hq.y));
    *(uint2*)(g_zh+i) = make_uint2(*(uint32_t*)&hp, *(uint32_t*)&hq);
    *(uint2*)(g_zl+i) = make_uint2(*(uint32_t*)&lp, *(uint32_t*)&lq);
}

// ---------------- elementwise: zt = lang * lang_out2 ----------------
__global__ void ztmul_kernel()
{
    size_t i = ((size_t)blockIdx.x*256 + threadIdx.x)*4;
    float4 a = *(const float4*)&g_lang[i];
    float4 b4 = *(const float4*)&g_lo2[i];
    float4 r; r.x=a.x*b4.x; r.y=a.y*b4.y; r.z=a.z*b4.z; r.w=a.w*b4.w;
    *(float4*)&g_zt[i] = r;
}

extern "C" void kernel_launch(void* const* d_in, const int* in_sizes, int n_in,
                              void* d_out, int out_size)
{
    const float* x      = (const float*)d_in[0];
    const float* l      = (const float*)d_in[1];
    const float* lmask  = (const float*)d_in[2];
    const float* w_vis  = (const float*)d_in[3];  const float* b_vis  = (const float*)d_in[4];
    const float* w_langp= (const float*)d_in[5];  const float* b_langp= (const float*)d_in[6];
    const float* w_q    = (const float*)d_in[7];  const float* b_q    = (const float*)d_in[8];
    const float* w_k    = (const float*)d_in[9];  const float* b_k    = (const float*)d_in[10];
    const float* w_v    = (const float*)d_in[11]; const float* b_v    = (const float*)d_in[12];
    const float* w_lv   = (const float*)d_in[13]; const float* b_lv   = (const float*)d_in[14];
    const float* w_W    = (const float*)d_in[15]; const float* b_W    = (const float*)d_in[16];
    const float* w_langW= (const float*)d_in[17]; const float* b_langW= (const float*)d_in[18];
    const float* w_mm   = (const float*)d_in[19]; const float* b_mm   = (const float*)d_in[20];
    const float* w_langmm=(const float*)d_in[21]; const float* b_langmm=(const float*)d_in[22];
    float* out = (float*)d_out;

    float *p_vis, *p_q, *p_lv, *p_vo, *p_lang, *p_k, *p_v, *p_lo1, *p_lo2, *p_zt;
    float *p_mq, *p_rq, *p_mlv, *p_rlv, *p_mw, *p_rw;
    __nv_bfloat16 *p_xh, *p_xl, *p_ath, *p_atl, *p_zh, *p_zl, *p_wh, *p_wl;
    cudaGetSymbolAddress((void**)&p_vis, g_vis);  cudaGetSymbolAddress((void**)&p_q,  g_q);
    cudaGetSymbolAddress((void**)&p_lv,  g_lv);   cudaGetSymbolAddress((void**)&p_vo, g_vo);
    cudaGetSymbolAddress((void**)&p_lang,g_lang); cudaGetSymbolAddress((void**)&p_k,  g_k);
    cudaGetSymbolAddress((void**)&p_v,   g_v);    cudaGetSymbolAddress((void**)&p_lo1,g_lo1);
    cudaGetSymbolAddress((void**)&p_lo2, g_lo2);  cudaGetSymbolAddress((void**)&p_zt, g_zt);
    cudaGetSymbolAddress((void**)&p_mq,  g_mq);   cudaGetSymbolAddress((void**)&p_rq, g_rq);
    cudaGetSymbolAddress((void**)&p_mlv, g_mlv);  cudaGetSymbolAddress((void**)&p_rlv,g_rlv);
    cudaGetSymbolAddress((void**)&p_mw,  g_mw);   cudaGetSymbolAddress((void**)&p_rw, g_rw);
    cudaGetSymbolAddress((void**)&p_xh,  g_xh);   cudaGetSymbolAddress((void**)&p_xl, g_xl);
    cudaGetSymbolAddress((void**)&p_ath, g_ath);  cudaGetSymbolAddress((void**)&p_atl,g_atl);
    cudaGetSymbolAddress((void**)&p_zh,  g_zh);   cudaGetSymbolAddress((void**)&p_zl, g_zl);
    cudaGetSymbolAddress((void**)&p_wh,  g_wh);   cudaGetSymbolAddress((void**)&p_wl, g_wl);

    cudaFuncSetAttribute(tc_gemm, cudaFuncAttributeMaxDynamicSharedMemorySize, SMEMB);

    dim3 blk256(256);
    // pre-convert x + weights to bf16 hi/lo
    cvt_split<<<(int)(((size_t)Mm*Dd)/1024), blk256>>>(x, p_xh, p_xl);
    cvt_split<<<262144/1024, blk256>>>(w_vis, p_wh+WOFF_VIS, p_wl+WOFF_VIS);
    cvt_split<<<262144/1024, blk256>>>(w_q,   p_wh+WOFF_Q,   p_wl+WOFF_Q);
    cvt_split<<<393216/1024, blk256>>>(w_lv,  p_wh+WOFF_LV,  p_wl+WOFF_LV);
    cvt_split<<<262144/1024, blk256>>>(w_W,   p_wh+WOFF_W,   p_wl+WOFF_W);
    cvt_split<<<262144/1024, blk256>>>(w_mm,  p_wh+WOFF_MM,  p_wl+WOFF_MM);
    // big GEMMs
    tc_gemm<<<dim3(Dd/128,  Mm/128), blk256, SMEMB>>>(p_xh, p_xl, p_wh+WOFF_VIS, p_wl+WOFF_VIS, b_vis, p_vis, Dd,  Dd, 1);
    tc_gemm<<<dim3(Kch/128, Mm/128), blk256, SMEMB>>>(p_xh, p_xl, p_wh+WOFF_Q,   p_wl+WOFF_Q,   b_q,   p_q,   Kch, Dd, 0);
    tc_gemm<<<dim3(CLd/128, Mm/128), blk256, SMEMB>>>(p_xh, p_xl, p_wh+WOFF_LV,  p_wl+WOFF_LV,  b_lv,  p_lv,  CLd, Dd, 0);
    stats_kernel<<<dim3(Kch/32, Bb), dim3(32,16)>>>(p_q,  p_mq,  p_rq,  Kch);
    stats_kernel<<<dim3(CLd/32, Bb), dim3(32,16)>>>(p_lv, p_mlv, p_rlv, CLd);
    // lang-side convs
    lang_conv_kernel<<<dim3(Bb, CLd/32), blk256>>>(l, w_langp, b_langp, lmask, p_lang, CLd, 1);
    lang_conv_kernel<<<dim3(Bb, Kch/32), blk256>>>(l, w_k, b_k, lmask, p_k, Kch, 2);
    lang_conv_kernel<<<dim3(Bb, Vch/32), blk256>>>(l, w_v, b_v, lmask, p_v, Vch, 2);
    // attention
    sim_kernel<<<dim3(HWd/1024, Bb*Hh), blk256>>>(lmask);
    latt_stats_kernel<<<Bb*Hh, dim3(32,32)>>>();
    attout_kernel<<<dim3(HWd/256, Bb*Hh), blk256>>>();
    langout_part_kernel<<<dim3(Bb*Hh, SPL), blk256>>>();
    lo1_reduce_kernel<<<(Bb*CLd*NLd)/256, blk256>>>(lmask);
    // lang_out2 = inorm(conv(lang_out, w_langW))
    lang_conv_kernel<<<dim3(Bb, CLd/32), blk256>>>(p_lo1, w_langW, b_langW, lmask, p_lo2, CLd, 8);
    // vis_out = inorm(conv(att_out, w_W))
    tc_gemm<<<dim3(Vch/128, Mm/128), blk256, SMEMB>>>(p_ath, p_atl, p_wh+WOFF_W, p_wl+WOFF_W, b_W, p_vo, Vch, Vch, 0);
    stats_kernel<<<dim3(Vch/32, Bb), dim3(32,16)>>>(p_vo, p_mw, p_rw, Vch);
    zmul_kernel<<<(int)(((size_t)Mm*Vch)/1024), blk256>>>();
    // mm = gelu(conv(z, w_mm)) -> out[0 : M*V]
    tc_gemm<<<dim3(Vch/128, Mm/128), blk256, SMEMB>>>(p_zh, p_zl, p_wh+WOFF_MM, p_wl+WOFF_MM, b_mm, out, Vch, Vch, 1);
    // lang_mm = gelu(conv(lang*lo2, w_langmm)) transposed -> out tail
    ztmul_kernel<<<(Bb*CLd*NLd)/1024, blk256>>>();
    lang_conv_kernel<<<dim3(Bb, CLd/32), blk256>>>(p_zt, w_langmm, b_langmm, lmask,
                                                   out + (size_t)Mm*Vch, CLd, 1|4);
    (void)in_sizes; (void)n_in; (void)out_size;
}